// round 4
// baseline (speedup 1.0000x reference)
#include <cuda_runtime.h>
#include <math.h>

#define NN 50000
#define EE 800000
#define SSED 8192
#define HD 64

// ---------------- scratch (device globals) ----------------------------------
__device__ float g_deg[3 * NN];
__device__ float g_invdeg[3 * NN];
__device__ float g_S[3][NN * HD];
__device__ float g_h1[NN * HD];
__device__ float g_h2[SSED * HD];
__device__ float g_hs[SSED * HD];
__device__ float g_zd1[3 * SSED * 256];
__device__ float g_zd2[3 * SSED * 32];
__device__ float g_yf1[3 * SSED * 256];
__device__ float g_yf2[3 * SSED * 2048];
__device__ int   g_ecnt[3];
__device__ long long g_epk[3][EE];   // packed (dst<<32)|src for dst<8192

// ---------------- utility kernels ------------------------------------------
__global__ void k_zero(float* __restrict__ p, long n) {
    long i = (long)blockIdx.x * blockDim.x + threadIdx.x;
    long st = (long)gridDim.x * blockDim.x;
    for (; i < n; i += st) p[i] = 0.f;
}

__global__ void k_deg(const int* __restrict__ d0, const int* __restrict__ d1,
                      const int* __restrict__ d2) {
    long i = (long)blockIdx.x * blockDim.x + threadIdx.x;
    if (i >= 3L * EE) return;
    int r = (int)(i / EE);
    int e = (int)(i % EE);
    const int* d = (r == 0) ? d0 : ((r == 1) ? d1 : d2);
    atomicAdd(&g_deg[r * NN + d[e]], 1.f);
}

__global__ void k_invdeg() {
    int i = blockIdx.x * blockDim.x + threadIdx.x;
    if (i < 3) g_ecnt[i] = 0;
    if (i < 3 * NN) g_invdeg[i] = 1.f / fmaxf(g_deg[i], 1.f);
}

// compact edges with dst < SSED (warp-aggregated append)
__global__ void k_compact(const int* __restrict__ s0, const int* __restrict__ d0,
                          const int* __restrict__ s1, const int* __restrict__ d1,
                          const int* __restrict__ s2, const int* __restrict__ d2) {
    const int r = blockIdx.y;
    const int* s = (r == 0) ? s0 : ((r == 1) ? s1 : s2);
    const int* d = (r == 0) ? d0 : ((r == 1) ? d1 : d2);
    int e = blockIdx.x * blockDim.x + threadIdx.x;
    bool keep = false;
    int dv = 0, sv = 0;
    if (e < EE) { dv = d[e]; sv = s[e]; keep = dv < SSED; }
    unsigned m = __ballot_sync(0xffffffffu, keep);
    int cnt = __popc(m);
    int base = 0;
    if ((threadIdx.x & 31) == 0 && cnt) base = atomicAdd(&g_ecnt[r], cnt);
    base = __shfl_sync(0xffffffffu, base, 0);
    if (keep) {
        int pos = base + __popc(m & ((1u << (threadIdx.x & 31)) - 1u));
        g_epk[r][pos] = (((long long)dv) << 32) | (unsigned)sv;
    }
}

// layer-1 scatter: all relations in one launch (blockIdx.y = r)
__global__ void k_scatter_all(const float* __restrict__ h,
                              const int* __restrict__ s0, const int* __restrict__ d0,
                              const int* __restrict__ s1, const int* __restrict__ d1,
                              const int* __restrict__ s2, const int* __restrict__ d2) {
    const int r = blockIdx.y;
    const int* src = (r == 0) ? s0 : ((r == 1) ? s1 : s2);
    const int* dst = (r == 0) ? d0 : ((r == 1) ? d1 : d2);
    float* S = g_S[r];
    long i = (long)blockIdx.x * blockDim.x + threadIdx.x;
    if (i >= (long)EE * 16) return;
    int e = (int)(i >> 4);
    int f = (int)(i & 15) << 2;
    float4 v = *(const float4*)(h + (long)src[e] * HD + f);
    float* p = S + (long)dst[e] * HD + f;
    asm volatile("red.global.add.v4.f32 [%0], {%1,%2,%3,%4};"
                 :: "l"(p), "f"(v.x), "f"(v.y), "f"(v.z), "f"(v.w)
                 : "memory");
}

// layer-2 scatter over compacted edges (grid-stride; count read on device)
__global__ void k_scatter_c(const float* __restrict__ h) {
    const int r = blockIdx.y;
    const long total = (long)g_ecnt[r] * 16;
    float* S = g_S[r];
    const long long* ep = g_epk[r];
    long st = (long)gridDim.x * blockDim.x;
    for (long i = (long)blockIdx.x * blockDim.x + threadIdx.x; i < total; i += st) {
        int e = (int)(i >> 4);
        int f = (int)(i & 15) << 2;
        long long pk = ep[e];
        int dv = (int)(pk >> 32);
        int sv = (int)(pk & 0xffffffffLL);
        float4 v = *(const float4*)(h + (long)sv * HD + f);
        float* p = S + (long)dv * HD + f;
        asm volatile("red.global.add.v4.f32 [%0], {%1,%2,%3,%4};"
                     :: "l"(p), "f"(v.x), "f"(v.y), "f"(v.z), "f"(v.w)
                     : "memory");
    }
}

// out[n][j] = relu(bias[j] + sum_r invdeg[r][n] * sum_k S_r[n][k] * W[r][k][j])
__global__ void k_combine(const float* __restrict__ W, const float* __restrict__ bias,
                          float* __restrict__ out, int nNodes) {
    extern __shared__ float sm[];
    float* sW = sm;
    float* sS = sm + 3 * HD * HD;
    for (int i = threadIdx.x; i < 3 * HD * HD; i += blockDim.x) sW[i] = W[i];
    __syncthreads();
    const int j = threadIdx.x & 63;
    const int ln = threadIdx.x >> 6;
    for (long n0 = (long)blockIdx.x * 4; n0 < nNodes; n0 += (long)gridDim.x * 4) {
        int n = (int)n0 + ln;
        if (n < nNodes) {
#pragma unroll
            for (int r = 0; r < 3; r++)
                sS[(ln * 3 + r) * HD + j] = g_S[r][(long)n * HD + j] * g_invdeg[r * NN + n];
        }
        __syncthreads();
        if (n < nNodes) {
            float acc = bias[j];
#pragma unroll
            for (int r = 0; r < 3; r++) {
#pragma unroll
                for (int k = 0; k < HD; k++)
                    acc = fmaf(sS[(ln * 3 + r) * HD + k], sW[(r * HD + k) * HD + j], acc);
            }
            out[(long)n * HD + j] = fmaxf(acc, 0.f);
        }
        __syncthreads();
    }
}

// g_hs = leaky_relu(g_h2 @ Wlin + blin) + noise
__global__ void k_final(const float* __restrict__ W, const float* __restrict__ bias,
                        const float* __restrict__ noise) {
    __shared__ float sW[HD * HD];
    __shared__ float sS[4 * HD];
    for (int i = threadIdx.x; i < HD * HD; i += blockDim.x) sW[i] = W[i];
    __syncthreads();
    const int j = threadIdx.x & 63;
    const int ln = threadIdx.x >> 6;
    for (int n0 = blockIdx.x * 4; n0 < SSED; n0 += gridDim.x * 4) {
        int n = n0 + ln;
        sS[ln * HD + j] = g_h2[(long)n * HD + j];
        __syncthreads();
        float acc = bias[j];
#pragma unroll
        for (int k = 0; k < HD; k++)
            acc = fmaf(sS[ln * HD + k], sW[k * HD + j], acc);
        float v = (acc > 0.f) ? acc : 0.01f * acc;
        g_hs[(long)n * HD + j] = v + noise[(long)n * HD + j];
        __syncthreads();
    }
}

// ---------------- TF32 tensor-core GEMM (128x128 CTA, 64x64 warp tile) ------
__device__ __forceinline__ void cp16(void* smem, const void* gmem, bool valid) {
    unsigned s = (unsigned)__cvta_generic_to_shared(smem);
    int sz = valid ? 16 : 0;
    asm volatile("cp.async.cg.shared.global [%0], [%1], 16, %2;"
                 :: "r"(s), "l"(gmem), "r"(sz) : "memory");
}
__device__ __forceinline__ unsigned tf32(float f) {
    unsigned u;
    asm("cvt.rna.tf32.f32 %0, %1;" : "=r"(u) : "f"(f));
    return u;
}
__device__ __forceinline__ void mma8(float* c, const unsigned* a, const unsigned* b) {
    asm volatile("mma.sync.aligned.m16n8k8.row.col.f32.tf32.tf32.f32 "
                 "{%0,%1,%2,%3}, {%4,%5,%6,%7}, {%8,%9}, {%0,%1,%2,%3};"
                 : "+f"(c[0]), "+f"(c[1]), "+f"(c[2]), "+f"(c[3])
                 : "r"(a[0]), "r"(a[1]), "r"(a[2]), "r"(a[3]), "r"(b[0]), "r"(b[1]));
}

#define AS_STRIDE 20
#define BS_STRIDE 136
// smem: As[2][128][20] + Bs[2][16][136] floats
#define GEMM_SMEM ((2 * 128 * AS_STRIDE + 2 * 16 * BS_STRIDE) * 4)

// C[r] = act(A[r] @ B[r] + bias[r]); M%128==0, K%16==0.
// 128 threads = 4 warps, each 64x64. ACT: 1=relu, 2=leaky, 3=tanh
template <int ACT>
__global__ void __launch_bounds__(128, 2)
k_tgemm(const float* __restrict__ Aall, const float* __restrict__ Ball,
        const float* __restrict__ biasAll, float* __restrict__ Call,
        int M, int N, int K, long sA, long sB, long sBias, long sC, int ldc) {
    const int r = blockIdx.z;
    const float* A = Aall + (long)r * sA;
    const float* B = Ball + (long)r * sB;
    const float* bias = biasAll + (long)r * sBias;
    float* C = Call + (long)r * sC;

    extern __shared__ float smx[];
    float (*As)[128][AS_STRIDE] = (float (*)[128][AS_STRIDE])smx;
    float (*Bs)[16][BS_STRIDE] = (float (*)[16][BS_STRIDE])(smx + 2 * 128 * AS_STRIDE);

    const int t = threadIdx.x;
    const int lane = t & 31;
    const int warp = t >> 5;
    const int wm = (warp >> 1) * 64;
    const int wn = (warp & 1) * 64;
    const long bm = (long)blockIdx.y * 128;
    const int bn = blockIdx.x * 128;

    // A tile: 128 rows x 16 cols; each thread: own row, 4 cp16
    const int aRow = t;
    // B tile: 16 rows x 128 cols; thread: row = t>>3, colBase = (t&7)*16, 4 cp16
    const int bRow = t >> 3;
    const int bColB = (t & 7) << 4;

    const int gid = lane >> 2;
    const int tig = lane & 3;

    float acc[4][8][4];
#pragma unroll
    for (int i = 0; i < 4; i++)
#pragma unroll
        for (int j = 0; j < 8; j++)
#pragma unroll
            for (int c = 0; c < 4; c++) acc[i][j][c] = 0.f;

    const int KT = K / 16;

    // prologue
    {
        const float* aP = A + (bm + aRow) * (long)K;
#pragma unroll
        for (int c = 0; c < 4; c++)
            cp16(&As[0][aRow][c * 4], aP + c * 4, true);
#pragma unroll
        for (int c = 0; c < 4; c++) {
            int col = bColB + c * 4;
            bool v = (bn + col) < N;
            cp16(&Bs[0][bRow][col], B + (long)bRow * N + (v ? bn + col : 0), v);
        }
        asm volatile("cp.async.commit_group;" ::: "memory");
        asm volatile("cp.async.wait_group 0;" ::: "memory");
        __syncthreads();
    }

    for (int kt = 0; kt < KT; kt++) {
        const int cb = kt & 1, nb = (kt + 1) & 1;
        if (kt + 1 < KT) {
            long ko = (long)(kt + 1) * 16;
            const float* aP = A + (bm + aRow) * (long)K + ko;
#pragma unroll
            for (int c = 0; c < 4; c++)
                cp16(&As[nb][aRow][c * 4], aP + c * 4, true);
#pragma unroll
            for (int c = 0; c < 4; c++) {
                int col = bColB + c * 4;
                bool v = (bn + col) < N;
                cp16(&Bs[nb][bRow][col], B + (ko + bRow) * (long)N + (v ? bn + col : 0), v);
            }
            asm volatile("cp.async.commit_group;" ::: "memory");
        }
#pragma unroll
        for (int k8 = 0; k8 < 2; k8++) {
            const int k0 = k8 * 8;
            unsigned a[4][4], b[8][2];
#pragma unroll
            for (int tm = 0; tm < 4; tm++) {
                int m = wm + tm * 16 + gid;
                a[tm][0] = tf32(As[cb][m][k0 + tig]);
                a[tm][1] = tf32(As[cb][m + 8][k0 + tig]);
                a[tm][2] = tf32(As[cb][m][k0 + tig + 4]);
                a[tm][3] = tf32(As[cb][m + 8][k0 + tig + 4]);
            }
#pragma unroll
            for (int tn = 0; tn < 8; tn++) {
                int n = wn + tn * 8 + gid;
                b[tn][0] = tf32(Bs[cb][k0 + tig][n]);
                b[tn][1] = tf32(Bs[cb][k0 + tig + 4][n]);
            }
#pragma unroll
            for (int tm = 0; tm < 4; tm++)
#pragma unroll
                for (int tn = 0; tn < 8; tn++)
                    mma8(acc[tm][tn], a[tm], b[tn]);
        }
        if (kt + 1 < KT)
            asm volatile("cp.async.wait_group 0;" ::: "memory");
        __syncthreads();
    }

    // epilogue
#pragma unroll
    for (int tm = 0; tm < 4; tm++) {
        long row0 = bm + wm + tm * 16 + gid;
#pragma unroll
        for (int tn = 0; tn < 8; tn++) {
            int col = bn + wn + tn * 8 + tig * 2;
            if (col < N) {
                float bs0 = bias[col], bs1 = bias[col + 1];
#pragma unroll
                for (int h = 0; h < 2; h++) {
                    long row = row0 + h * 8;
                    float u0 = acc[tm][tn][h * 2 + 0] + bs0;
                    float u1 = acc[tm][tn][h * 2 + 1] + bs1;
                    if (ACT == 1) { u0 = fmaxf(u0, 0.f); u1 = fmaxf(u1, 0.f); }
                    else if (ACT == 2) { u0 = (u0 > 0.f) ? u0 : 0.01f * u0;
                                         u1 = (u1 > 0.f) ? u1 : 0.01f * u1; }
                    else { u0 = tanhf(u0); u1 = tanhf(u1); }
                    C[row * ldc + col] = u0;
                    C[row * ldc + col + 1] = u1;
                }
            }
        }
    }
}

// ---------------- small 64x64 SGEMM (N=32 case) ----------------------------
template <int ACT>
__global__ void k_sgemm(const float* __restrict__ Aall, const float* __restrict__ Ball,
                        const float* __restrict__ biasAll, float* __restrict__ Call,
                        int M, int N, int K,
                        long sA, long sB, long sBias, long sC, int ldc) {
    const int r = blockIdx.z;
    const float* A = Aall + (long)r * sA;
    const float* B = Ball + (long)r * sB;
    const float* bias = biasAll + (long)r * sBias;
    float* C = Call + (long)r * sC;

    __shared__ float As[16][65];
    __shared__ float Bs[16][64];

    const int tid = threadIdx.x;
    const int bm = blockIdx.y * 64;
    const int bn = blockIdx.x * 64;

    const int aRow = tid >> 2;
    const int aCol = (tid & 3) << 2;
    const int bRow = tid >> 4;
    const int bCol = (tid & 15) << 2;

    const int tx = tid & 15;
    const int ty = tid >> 4;

    float acc[4][4];
#pragma unroll
    for (int m = 0; m < 4; m++)
#pragma unroll
        for (int n = 0; n < 4; n++) acc[m][n] = 0.f;

    for (int k0 = 0; k0 < K; k0 += 16) {
        float4 av = *(const float4*)(A + (long)(bm + aRow) * K + k0 + aCol);
        As[aCol + 0][aRow] = av.x;
        As[aCol + 1][aRow] = av.y;
        As[aCol + 2][aRow] = av.z;
        As[aCol + 3][aRow] = av.w;
        if (bn + bCol + 3 < N) {
            *(float4*)(&Bs[bRow][bCol]) =
                *(const float4*)(B + (long)(k0 + bRow) * N + bn + bCol);
        } else {
#pragma unroll
            for (int i2 = 0; i2 < 4; i2++)
                Bs[bRow][bCol + i2] =
                    (bn + bCol + i2 < N) ? B[(long)(k0 + bRow) * N + bn + bCol + i2] : 0.f;
        }
        __syncthreads();
#pragma unroll
        for (int k = 0; k < 16; k++) {
            float a0 = As[k][ty * 4 + 0], a1 = As[k][ty * 4 + 1];
            float a2 = As[k][ty * 4 + 2], a3 = As[k][ty * 4 + 3];
            float b0 = Bs[k][tx * 4 + 0], b1 = Bs[k][tx * 4 + 1];
            float b2 = Bs[k][tx * 4 + 2], b3 = Bs[k][tx * 4 + 3];
            acc[0][0] = fmaf(a0, b0, acc[0][0]); acc[0][1] = fmaf(a0, b1, acc[0][1]);
            acc[0][2] = fmaf(a0, b2, acc[0][2]); acc[0][3] = fmaf(a0, b3, acc[0][3]);
            acc[1][0] = fmaf(a1, b0, acc[1][0]); acc[1][1] = fmaf(a1, b1, acc[1][1]);
            acc[1][2] = fmaf(a1, b2, acc[1][2]); acc[1][3] = fmaf(a1, b3, acc[1][3]);
            acc[2][0] = fmaf(a2, b0, acc[2][0]); acc[2][1] = fmaf(a2, b1, acc[2][1]);
            acc[2][2] = fmaf(a2, b2, acc[2][2]); acc[2][3] = fmaf(a2, b3, acc[2][3]);
            acc[3][0] = fmaf(a3, b0, acc[3][0]); acc[3][1] = fmaf(a3, b1, acc[3][1]);
            acc[3][2] = fmaf(a3, b2, acc[3][2]); acc[3][3] = fmaf(a3, b3, acc[3][3]);
        }
        __syncthreads();
    }
#pragma unroll
    for (int m = 0; m < 4; m++) {
        int row = bm + ty * 4 + m;
#pragma unroll
        for (int n = 0; n < 4; n++) {
            int col = bn + tx * 4 + n;
            if (col < N) {
                float v = acc[m][n] + bias[col];
                if (ACT == 1) v = fmaxf(v, 0.f);
                else if (ACT == 2) v = (v > 0.f) ? v : 0.01f * v;
                else if (ACT == 3) v = tanhf(v);
                C[(long)row * ldc + col] = v;
            }
        }
    }
}

// pred_missing head
__global__ void k_dw3(const float* __restrict__ z, const float* __restrict__ W,
                      const float* __restrict__ b, float* __restrict__ out) {
    int i = blockIdx.x * blockDim.x + threadIdx.x;
    if (i >= 3 * SSED) return;
    int r = i / SSED;
    int s = i % SSED;
    const float* zz = z + ((long)r * SSED + s) * 32;
    const float* w = W + r * 32;
    float acc = b[r];
#pragma unroll
    for (int k = 0; k < 32; k++) acc = fmaf(zz[k], w[k], acc);
    out[((long)r * SSED + s) * 321] = fmaxf(acc, 0.f);
}

// ---------------- host launch ----------------------------------------------
extern "C" void kernel_launch(void* const* d_in, const int* in_sizes, int n_in,
                              void* d_out, int out_size) {
    static const int MAP_DICT[27] = {0,1,2,3,4,5,6,7,8,9,10,11,12,13,14,15,16,17,18,19,20,21,22,23,24,25,26};
    static const int MAP_SIG[27]  = {0,1,20,21,22,23,24,25,26,2,3,4,5,6,7,8,9,10,11,12,13,14,15,16,17,18,19};
    static const int MAP_ALPHA[27]= {26,21,22,23,12,24,13,25,14,0,3,1,4,2,5,6,9,7,10,8,11,15,18,16,19,17,20};
    const int* MAP = MAP_DICT;
    if (n_in >= 3) {
        if (in_sizes[2] == 12288) MAP = MAP_SIG;
        else if (in_sizes[2] == 4096) MAP = MAP_ALPHA;
    }

    const float* x     = (const float*)d_in[MAP[0]];
    const float* noise = (const float*)d_in[MAP[1]];
    const int* src[3]  = {(const int*)d_in[MAP[3]], (const int*)d_in[MAP[5]], (const int*)d_in[MAP[7]]};
    const int* dst[3]  = {(const int*)d_in[MAP[4]], (const int*)d_in[MAP[6]], (const int*)d_in[MAP[8]]};
    const float* Wc1   = (const float*)d_in[MAP[9]];
    const float* bc1   = (const float*)d_in[MAP[10]];
    const float* Wc2   = (const float*)d_in[MAP[11]];
    const float* bc2   = (const float*)d_in[MAP[12]];
    const float* Wlin  = (const float*)d_in[MAP[13]];
    const float* blin  = (const float*)d_in[MAP[14]];
    const float* dW1   = (const float*)d_in[MAP[15]];
    const float* db1   = (const float*)d_in[MAP[16]];
    const float* dW2   = (const float*)d_in[MAP[17]];
    const float* db2   = (const float*)d_in[MAP[18]];
    const float* dW3   = (const float*)d_in[MAP[19]];
    const float* db3   = (const float*)d_in[MAP[20]];
    const float* fW1   = (const float*)d_in[MAP[21]];
    const float* fb1   = (const float*)d_in[MAP[22]];
    const float* fW2   = (const float*)d_in[MAP[23]];
    const float* fb2   = (const float*)d_in[MAP[24]];
    const float* fW3   = (const float*)d_in[MAP[25]];
    const float* fb3   = (const float*)d_in[MAP[26]];
    float* out = (float*)d_out;

    float *pDeg, *pS, *pH1, *pH2, *pHs, *pZ1, *pZ2, *pY1, *pY2;
    cudaGetSymbolAddress((void**)&pDeg, g_deg);
    cudaGetSymbolAddress((void**)&pS,   g_S);
    cudaGetSymbolAddress((void**)&pH1,  g_h1);
    cudaGetSymbolAddress((void**)&pH2,  g_h2);
    cudaGetSymbolAddress((void**)&pHs,  g_hs);
    cudaGetSymbolAddress((void**)&pZ1,  g_zd1);
    cudaGetSymbolAddress((void**)&pZ2,  g_zd2);
    cudaGetSymbolAddress((void**)&pY1,  g_yf1);
    cudaGetSymbolAddress((void**)&pY2,  g_yf2);
    float* pSr[3] = {pS, pS + (long)NN * HD, pS + 2L * NN * HD};

    cudaFuncSetAttribute(k_combine, cudaFuncAttributeMaxDynamicSharedMemorySize, 53248);
    const int SMEM_COMBINE = (3 * HD * HD + 4 * 3 * HD) * sizeof(float);

    // degrees + edge compaction for layer 2
    k_zero<<<1024, 256>>>(pDeg, 3L * NN);
    k_deg<<<(3 * EE + 255) / 256, 256>>>(dst[0], dst[1], dst[2]);
    k_invdeg<<<(3 * NN + 255) / 256, 256>>>();
    {
        dim3 gc((EE + 255) / 256, 3);
        k_compact<<<gc, 256>>>(src[0], dst[0], src[1], dst[1], src[2], dst[2]);
    }

    // ----- conv layer 1 -----
    k_zero<<<4096, 256>>>(pS, 3L * NN * HD);
    {
        dim3 gs((EE * 16) / 256, 3);
        k_scatter_all<<<gs, 256>>>(x, src[0], dst[0], src[1], dst[1], src[2], dst[2]);
    }
    k_combine<<<12500, 256, SMEM_COMBINE>>>(Wc1, bc1, pH1, NN);

    // ----- conv layer 2 (compacted, dst < 8192) -----
    for (int r = 0; r < 3; r++)
        k_zero<<<512, 256>>>(pSr[r], (long)SSED * HD);
    {
        dim3 gs(3072, 3);
        k_scatter_c<<<gs, 256>>>(pH1);
    }
    k_combine<<<2048, 256, SMEM_COMBINE>>>(Wc2, bc2, pH2, SSED);

    // ----- final linear -----
    k_final<<<2048, 256>>>(Wlin, blin, noise);

    // ----- decoder: pred_missing -----
    dim3 g1(2, SSED / 128, 3);    // N=256
    k_tgemm<2><<<g1, 128, GEMM_SMEM>>>(pHs, dW1, db1, pZ1, SSED, 256, 64,
                                       0, (long)64 * 256, 256, (long)SSED * 256, 256);
    dim3 g2(1, SSED / 64, 3);     // N=32
    k_sgemm<2><<<g2, 256>>>(pZ1, dW2, db2, pZ2, SSED, 32, 256,
                            (long)SSED * 256, (long)256 * 32, 32, (long)SSED * 32, 32);
    k_dw3<<<(3 * SSED + 255) / 256, 256>>>(pZ2, dW3, db3, out);

    // ----- decoder: pred_feat -----
    k_tgemm<1><<<g1, 128, GEMM_SMEM>>>(pHs, fW1, fb1, pY1, SSED, 256, 64,
                                       0, (long)64 * 256, 256, (long)SSED * 256, 256);
    dim3 g3(16, SSED / 128, 3);   // N=2048
    k_tgemm<1><<<g3, 128, GEMM_SMEM>>>(pY1, fW2, fb2, pY2, SSED, 2048, 256,
                                       (long)SSED * 256, (long)256 * 2048, 2048,
                                       (long)SSED * 2048, 2048);
    dim3 g4(3, SSED / 128, 3);    // N=320
    k_tgemm<3><<<g4, 128, GEMM_SMEM>>>(pY2, fW3, fb3, out + 1, SSED, 320, 2048,
                                       (long)SSED * 2048, (long)2048 * 320, 320,
                                       (long)SSED * 321, 321);
}

// round 5
// speedup vs baseline: 1.2516x; 1.2516x over previous
#include <cuda_runtime.h>
#include <math.h>

#define NN 50000
#define EE 800000
#define SSED 8192
#define HD 64

// ---------------- scratch (device globals) ----------------------------------
__device__ int   g_off[3][NN + 1];
__device__ int   g_cur[3 * NN];       // counts, then cursors
__device__ int   g_esrc[3][EE];       // CSR: src indices grouped by dst
__device__ float g_S[3][NN * HD];     // normalized per-relation aggregates
__device__ float g_h1[NN * HD];
__device__ float g_h2[SSED * HD];
__device__ float g_hs[SSED * HD];
__device__ float g_zd1[3 * SSED * 256];
__device__ float g_zd2[3 * SSED * 32];
__device__ float g_yf1[3 * SSED * 256];
__device__ float g_yf2[3 * SSED * 2048];

// ---------------- CSR construction ------------------------------------------
__global__ void k_zeroi(int* __restrict__ p, int n) {
    int i = blockIdx.x * blockDim.x + threadIdx.x;
    if (i < n) p[i] = 0;
}

__global__ void k_cnt(const int* __restrict__ d0, const int* __restrict__ d1,
                      const int* __restrict__ d2) {
    const int r = blockIdx.y;
    const int* d = (r == 0) ? d0 : ((r == 1) ? d1 : d2);
    int e = blockIdx.x * blockDim.x + threadIdx.x;
    if (e < EE) atomicAdd(&g_cur[r * NN + d[e]], 1);
}

// one block (1024 thr) per relation: exclusive scan of counts -> g_off,
// zero the counters for reuse as fill cursors.
__global__ void k_scan() {
    const int r = blockIdx.x;
    __shared__ int sm[1024];
    __shared__ int sbase;
    if (threadIdx.x == 0) sbase = 0;
    __syncthreads();
    for (int c = 0; c < NN; c += 1024) {
        int i = c + threadIdx.x;
        int v = (i < NN) ? g_cur[r * NN + i] : 0;
        sm[threadIdx.x] = v;
        __syncthreads();
#pragma unroll
        for (int o = 1; o < 1024; o <<= 1) {
            int t2 = (threadIdx.x >= o) ? sm[threadIdx.x - o] : 0;
            __syncthreads();
            sm[threadIdx.x] += t2;
            __syncthreads();
        }
        if (i < NN) {
            g_off[r][i] = sbase + sm[threadIdx.x] - v;
            g_cur[r * NN + i] = 0;
        }
        __syncthreads();
        if (threadIdx.x == 1023) sbase += sm[1023];
        __syncthreads();
    }
    if (threadIdx.x == 0) g_off[r][NN] = sbase;
}

__global__ void k_fill(const int* __restrict__ s0, const int* __restrict__ d0,
                       const int* __restrict__ s1, const int* __restrict__ d1,
                       const int* __restrict__ s2, const int* __restrict__ d2) {
    const int r = blockIdx.y;
    const int* s = (r == 0) ? s0 : ((r == 1) ? s1 : s2);
    const int* d = (r == 0) ? d0 : ((r == 1) ? d1 : d2);
    int e = blockIdx.x * blockDim.x + threadIdx.x;
    if (e < EE) {
        int dv = d[e];
        int pos = g_off[r][dv] + atomicAdd(&g_cur[r * NN + dv], 1);
        g_esrc[r][pos] = s[e];
    }
}

// gather: S[r][n] = (1/max(deg,1)) * sum_{e: dst=n} h[src_e]; 16 thr per node
__global__ void k_gather(const float* __restrict__ h, int nLimit) {
    const int r = blockIdx.y;
    int node = blockIdx.x * 16 + (threadIdx.x >> 4);
    if (node >= nLimit) return;
    const int q = (threadIdx.x & 15) << 2;
    const int b = g_off[r][node], e2 = g_off[r][node + 1];
    const int* es = g_esrc[r];
    float4 acc = make_float4(0.f, 0.f, 0.f, 0.f);
    for (int i = b; i < e2; i++) {
        int s = __ldg(es + i);
        float4 v = *(const float4*)(h + (long)s * HD + q);
        acc.x += v.x; acc.y += v.y; acc.z += v.z; acc.w += v.w;
    }
    float inv = (e2 > b) ? 1.f / (float)(e2 - b) : 1.f;
    acc.x *= inv; acc.y *= inv; acc.z *= inv; acc.w *= inv;
    *(float4*)(g_S[r] + (long)node * HD + q) = acc;
}

// out[n][j] = relu(bias[j] + sum_r sum_k S_r[n][k] * W[r][k][j])  (S normalized)
__global__ void k_combine(const float* __restrict__ W, const float* __restrict__ bias,
                          float* __restrict__ out, int nNodes) {
    extern __shared__ float sm[];
    float* sW = sm;
    float* sS = sm + 3 * HD * HD;
    for (int i = threadIdx.x; i < 3 * HD * HD; i += blockDim.x) sW[i] = W[i];
    __syncthreads();
    const int j = threadIdx.x & 63;
    const int ln = threadIdx.x >> 6;
    for (long n0 = (long)blockIdx.x * 4; n0 < nNodes; n0 += (long)gridDim.x * 4) {
        int n = (int)n0 + ln;
        if (n < nNodes) {
#pragma unroll
            for (int r = 0; r < 3; r++)
                sS[(ln * 3 + r) * HD + j] = g_S[r][(long)n * HD + j];
        }
        __syncthreads();
        if (n < nNodes) {
            float acc = bias[j];
#pragma unroll
            for (int r = 0; r < 3; r++) {
#pragma unroll
                for (int k = 0; k < HD; k++)
                    acc = fmaf(sS[(ln * 3 + r) * HD + k], sW[(r * HD + k) * HD + j], acc);
            }
            out[(long)n * HD + j] = fmaxf(acc, 0.f);
        }
        __syncthreads();
    }
}

// g_hs = leaky_relu(g_h2 @ Wlin + blin) + noise
__global__ void k_final(const float* __restrict__ W, const float* __restrict__ bias,
                        const float* __restrict__ noise) {
    __shared__ float sW[HD * HD];
    __shared__ float sS[4 * HD];
    for (int i = threadIdx.x; i < HD * HD; i += blockDim.x) sW[i] = W[i];
    __syncthreads();
    const int j = threadIdx.x & 63;
    const int ln = threadIdx.x >> 6;
    for (int n0 = blockIdx.x * 4; n0 < SSED; n0 += gridDim.x * 4) {
        int n = n0 + ln;
        sS[ln * HD + j] = g_h2[(long)n * HD + j];
        __syncthreads();
        float acc = bias[j];
#pragma unroll
        for (int k = 0; k < HD; k++)
            acc = fmaf(sS[ln * HD + k], sW[k * HD + j], acc);
        float v = (acc > 0.f) ? acc : 0.01f * acc;
        g_hs[(long)n * HD + j] = v + noise[(long)n * HD + j];
        __syncthreads();
    }
}

// ---------------- TF32 tensor-core GEMM (R3 config: 256 thr, 64x32 warp) ----
__device__ __forceinline__ void cp16(void* smem, const void* gmem, bool valid) {
    unsigned s = (unsigned)__cvta_generic_to_shared(smem);
    int sz = valid ? 16 : 0;
    asm volatile("cp.async.cg.shared.global [%0], [%1], 16, %2;"
                 :: "r"(s), "l"(gmem), "r"(sz) : "memory");
}
__device__ __forceinline__ unsigned tf32(float f) {
    unsigned u;
    asm("cvt.rna.tf32.f32 %0, %1;" : "=r"(u) : "f"(f));
    return u;
}
__device__ __forceinline__ void mma8(float* c, const unsigned* a, const unsigned* b) {
    asm volatile("mma.sync.aligned.m16n8k8.row.col.f32.tf32.tf32.f32 "
                 "{%0,%1,%2,%3}, {%4,%5,%6,%7}, {%8,%9}, {%0,%1,%2,%3};"
                 : "+f"(c[0]), "+f"(c[1]), "+f"(c[2]), "+f"(c[3])
                 : "r"(a[0]), "r"(a[1]), "r"(a[2]), "r"(a[3]), "r"(b[0]), "r"(b[1]));
}

template <int ACT>
__global__ void __launch_bounds__(256, 2)
k_tgemm(const float* __restrict__ Aall, const float* __restrict__ Ball,
        const float* __restrict__ biasAll, float* __restrict__ Call,
        int M, int N, int K, long sA, long sB, long sBias, long sC, int ldc) {
    const int r = blockIdx.z;
    const float* A = Aall + (long)r * sA;
    const float* B = Ball + (long)r * sB;
    const float* bias = biasAll + (long)r * sBias;
    float* C = Call + (long)r * sC;

    __shared__ float As[2][128][20];
    __shared__ float Bs[2][16][136];

    const int t = threadIdx.x;
    const int lane = t & 31;
    const int warp = t >> 5;
    const int wm = (warp >> 2) * 64;
    const int wn = (warp & 3) * 32;
    const long bm = (long)blockIdx.y * 128;
    const int bn = blockIdx.x * 128;

    const int aRow = t >> 2;
    const int aCol = (t & 3) << 2;
    const int bRow = t >> 5;
    const int bCol = (t & 31) << 2;
    const bool bValid = (bn + bCol) < N;
    const int bnc = bValid ? bn + bCol : 0;

    const int gid = lane >> 2;
    const int tig = lane & 3;

    float acc[4][4][4];
#pragma unroll
    for (int i = 0; i < 4; i++)
#pragma unroll
        for (int j = 0; j < 4; j++)
#pragma unroll
            for (int c = 0; c < 4; c++) acc[i][j][c] = 0.f;

    const int KT = K / 16;

    {
        cp16(&As[0][aRow][aCol], A + (bm + aRow) * (long)K + aCol, true);
        cp16(&As[0][aRow + 64][aCol], A + (bm + aRow + 64) * (long)K + aCol, true);
        cp16(&Bs[0][bRow][bCol], B + (long)bRow * N + bnc, bValid);
        cp16(&Bs[0][bRow + 8][bCol], B + (long)(bRow + 8) * N + bnc, bValid);
        asm volatile("cp.async.commit_group;" ::: "memory");
        asm volatile("cp.async.wait_group 0;" ::: "memory");
        __syncthreads();
    }

    for (int kt = 0; kt < KT; kt++) {
        const int cb = kt & 1, nb = (kt + 1) & 1;
        if (kt + 1 < KT) {
            long ko = (long)(kt + 1) * 16;
            cp16(&As[nb][aRow][aCol], A + (bm + aRow) * (long)K + ko + aCol, true);
            cp16(&As[nb][aRow + 64][aCol], A + (bm + aRow + 64) * (long)K + ko + aCol, true);
            cp16(&Bs[nb][bRow][bCol], B + (ko + bRow) * (long)N + bnc, bValid);
            cp16(&Bs[nb][bRow + 8][bCol], B + (ko + bRow + 8) * (long)N + bnc, bValid);
            asm volatile("cp.async.commit_group;" ::: "memory");
        }
#pragma unroll
        for (int k8 = 0; k8 < 2; k8++) {
            const int k0 = k8 * 8;
            unsigned a[4][4], b[4][2];
#pragma unroll
            for (int tm = 0; tm < 4; tm++) {
                int m = wm + tm * 16 + gid;
                a[tm][0] = tf32(As[cb][m][k0 + tig]);
                a[tm][1] = tf32(As[cb][m + 8][k0 + tig]);
                a[tm][2] = tf32(As[cb][m][k0 + tig + 4]);
                a[tm][3] = tf32(As[cb][m + 8][k0 + tig + 4]);
            }
#pragma unroll
            for (int tn = 0; tn < 4; tn++) {
                int n = wn + tn * 8 + gid;
                b[tn][0] = tf32(Bs[cb][k0 + tig][n]);
                b[tn][1] = tf32(Bs[cb][k0 + tig + 4][n]);
            }
#pragma unroll
            for (int tm = 0; tm < 4; tm++)
#pragma unroll
                for (int tn = 0; tn < 4; tn++)
                    mma8(acc[tm][tn], a[tm], b[tn]);
        }
        if (kt + 1 < KT)
            asm volatile("cp.async.wait_group 0;" ::: "memory");
        __syncthreads();
    }

#pragma unroll
    for (int tm = 0; tm < 4; tm++) {
        long row0 = bm + wm + tm * 16 + gid;
#pragma unroll
        for (int tn = 0; tn < 4; tn++) {
            int col = bn + wn + tn * 8 + tig * 2;
            if (col < N) {
                float bs0 = bias[col], bs1 = bias[col + 1];
#pragma unroll
                for (int h = 0; h < 2; h++) {
                    long row = row0 + h * 8;
                    float u0 = acc[tm][tn][h * 2 + 0] + bs0;
                    float u1 = acc[tm][tn][h * 2 + 1] + bs1;
                    if (ACT == 1) { u0 = fmaxf(u0, 0.f); u1 = fmaxf(u1, 0.f); }
                    else if (ACT == 2) { u0 = (u0 > 0.f) ? u0 : 0.01f * u0;
                                         u1 = (u1 > 0.f) ? u1 : 0.01f * u1; }
                    else { u0 = tanhf(u0); u1 = tanhf(u1); }
                    C[row * ldc + col] = u0;
                    C[row * ldc + col + 1] = u1;
                }
            }
        }
    }
}

// ---------------- small 64x64 SGEMM (N=32 case) ----------------------------
template <int ACT>
__global__ void k_sgemm(const float* __restrict__ Aall, const float* __restrict__ Ball,
                        const float* __restrict__ biasAll, float* __restrict__ Call,
                        int M, int N, int K,
                        long sA, long sB, long sBias, long sC, int ldc) {
    const int r = blockIdx.z;
    const float* A = Aall + (long)r * sA;
    const float* B = Ball + (long)r * sB;
    const float* bias = biasAll + (long)r * sBias;
    float* C = Call + (long)r * sC;

    __shared__ float As[16][65];
    __shared__ float Bs[16][64];

    const int tid = threadIdx.x;
    const int bm = blockIdx.y * 64;
    const int bn = blockIdx.x * 64;

    const int aRow = tid >> 2;
    const int aCol = (tid & 3) << 2;
    const int bRow = tid >> 4;
    const int bCol = (tid & 15) << 2;

    const int tx = tid & 15;
    const int ty = tid >> 4;

    float acc[4][4];
#pragma unroll
    for (int m = 0; m < 4; m++)
#pragma unroll
        for (int n = 0; n < 4; n++) acc[m][n] = 0.f;

    for (int k0 = 0; k0 < K; k0 += 16) {
        float4 av = *(const float4*)(A + (long)(bm + aRow) * K + k0 + aCol);
        As[aCol + 0][aRow] = av.x;
        As[aCol + 1][aRow] = av.y;
        As[aCol + 2][aRow] = av.z;
        As[aCol + 3][aRow] = av.w;
        if (bn + bCol + 3 < N) {
            *(float4*)(&Bs[bRow][bCol]) =
                *(const float4*)(B + (long)(k0 + bRow) * N + bn + bCol);
        } else {
#pragma unroll
            for (int i2 = 0; i2 < 4; i2++)
                Bs[bRow][bCol + i2] =
                    (bn + bCol + i2 < N) ? B[(long)(k0 + bRow) * N + bn + bCol + i2] : 0.f;
        }
        __syncthreads();
#pragma unroll
        for (int k = 0; k < 16; k++) {
            float a0 = As[k][ty * 4 + 0], a1 = As[k][ty * 4 + 1];
            float a2 = As[k][ty * 4 + 2], a3 = As[k][ty * 4 + 3];
            float b0 = Bs[k][tx * 4 + 0], b1 = Bs[k][tx * 4 + 1];
            float b2 = Bs[k][tx * 4 + 2], b3 = Bs[k][tx * 4 + 3];
            acc[0][0] = fmaf(a0, b0, acc[0][0]); acc[0][1] = fmaf(a0, b1, acc[0][1]);
            acc[0][2] = fmaf(a0, b2, acc[0][2]); acc[0][3] = fmaf(a0, b3, acc[0][3]);
            acc[1][0] = fmaf(a1, b0, acc[1][0]); acc[1][1] = fmaf(a1, b1, acc[1][1]);
            acc[1][2] = fmaf(a1, b2, acc[1][2]); acc[1][3] = fmaf(a1, b3, acc[1][3]);
            acc[2][0] = fmaf(a2, b0, acc[2][0]); acc[2][1] = fmaf(a2, b1, acc[2][1]);
            acc[2][2] = fmaf(a2, b2, acc[2][2]); acc[2][3] = fmaf(a2, b3, acc[2][3]);
            acc[3][0] = fmaf(a3, b0, acc[3][0]); acc[3][1] = fmaf(a3, b1, acc[3][1]);
            acc[3][2] = fmaf(a3, b2, acc[3][2]); acc[3][3] = fmaf(a3, b3, acc[3][3]);
        }
        __syncthreads();
    }
#pragma unroll
    for (int m = 0; m < 4; m++) {
        int row = bm + ty * 4 + m;
#pragma unroll
        for (int n = 0; n < 4; n++) {
            int col = bn + tx * 4 + n;
            if (col < N) {
                float v = acc[m][n] + bias[col];
                if (ACT == 1) v = fmaxf(v, 0.f);
                else if (ACT == 2) v = (v > 0.f) ? v : 0.01f * v;
                else if (ACT == 3) v = tanhf(v);
                C[(long)row * ldc + col] = v;
            }
        }
    }
}

// pred_missing head
__global__ void k_dw3(const float* __restrict__ z, const float* __restrict__ W,
                      const float* __restrict__ b, float* __restrict__ out) {
    int i = blockIdx.x * blockDim.x + threadIdx.x;
    if (i >= 3 * SSED) return;
    int r = i / SSED;
    int s = i % SSED;
    const float* zz = z + ((long)r * SSED + s) * 32;
    const float* w = W + r * 32;
    float acc = b[r];
#pragma unroll
    for (int k = 0; k < 32; k++) acc = fmaf(zz[k], w[k], acc);
    out[((long)r * SSED + s) * 321] = fmaxf(acc, 0.f);
}

// ---------------- host launch ----------------------------------------------
extern "C" void kernel_launch(void* const* d_in, const int* in_sizes, int n_in,
                              void* d_out, int out_size) {
    static const int MAP_DICT[27] = {0,1,2,3,4,5,6,7,8,9,10,11,12,13,14,15,16,17,18,19,20,21,22,23,24,25,26};
    static const int MAP_SIG[27]  = {0,1,20,21,22,23,24,25,26,2,3,4,5,6,7,8,9,10,11,12,13,14,15,16,17,18,19};
    static const int MAP_ALPHA[27]= {26,21,22,23,12,24,13,25,14,0,3,1,4,2,5,6,9,7,10,8,11,15,18,16,19,17,20};
    const int* MAP = MAP_DICT;
    if (n_in >= 3) {
        if (in_sizes[2] == 12288) MAP = MAP_SIG;
        else if (in_sizes[2] == 4096) MAP = MAP_ALPHA;
    }

    const float* x     = (const float*)d_in[MAP[0]];
    const float* noise = (const float*)d_in[MAP[1]];
    const int* src[3]  = {(const int*)d_in[MAP[3]], (const int*)d_in[MAP[5]], (const int*)d_in[MAP[7]]};
    const int* dst[3]  = {(const int*)d_in[MAP[4]], (const int*)d_in[MAP[6]], (const int*)d_in[MAP[8]]};
    const float* Wc1   = (const float*)d_in[MAP[9]];
    const float* bc1   = (const float*)d_in[MAP[10]];
    const float* Wc2   = (const float*)d_in[MAP[11]];
    const float* bc2   = (const float*)d_in[MAP[12]];
    const float* Wlin  = (const float*)d_in[MAP[13]];
    const float* blin  = (const float*)d_in[MAP[14]];
    const float* dW1   = (const float*)d_in[MAP[15]];
    const float* db1   = (const float*)d_in[MAP[16]];
    const float* dW2   = (const float*)d_in[MAP[17]];
    const float* db2   = (const float*)d_in[MAP[18]];
    const float* dW3   = (const float*)d_in[MAP[19]];
    const float* db3   = (const float*)d_in[MAP[20]];
    const float* fW1   = (const float*)d_in[MAP[21]];
    const float* fb1   = (const float*)d_in[MAP[22]];
    const float* fW2   = (const float*)d_in[MAP[23]];
    const float* fb2   = (const float*)d_in[MAP[24]];
    const float* fW3   = (const float*)d_in[MAP[25]];
    const float* fb3   = (const float*)d_in[MAP[26]];
    float* out = (float*)d_out;

    int* pCur;
    float *pH1, *pH2, *pHs, *pZ1, *pZ2, *pY1, *pY2;
    cudaGetSymbolAddress((void**)&pCur, g_cur);
    cudaGetSymbolAddress((void**)&pH1,  g_h1);
    cudaGetSymbolAddress((void**)&pH2,  g_h2);
    cudaGetSymbolAddress((void**)&pHs,  g_hs);
    cudaGetSymbolAddress((void**)&pZ1,  g_zd1);
    cudaGetSymbolAddress((void**)&pZ2,  g_zd2);
    cudaGetSymbolAddress((void**)&pY1,  g_yf1);
    cudaGetSymbolAddress((void**)&pY2,  g_yf2);

    cudaFuncSetAttribute(k_combine, cudaFuncAttributeMaxDynamicSharedMemorySize, 53248);
    const int SMEM_COMBINE = (3 * HD * HD + 4 * 3 * HD) * sizeof(float);

    // ----- CSR build (counts -> scan -> fill) -----
    k_zeroi<<<(3 * NN + 255) / 256, 256>>>(pCur, 3 * NN);
    {
        dim3 g((EE + 255) / 256, 3);
        k_cnt<<<g, 256>>>(dst[0], dst[1], dst[2]);
        k_scan<<<3, 1024>>>();
        k_fill<<<g, 256>>>(src[0], dst[0], src[1], dst[1], src[2], dst[2]);
    }

    // ----- conv layer 1: gather over all nodes -----
    {
        dim3 g((NN + 15) / 16, 3);
        k_gather<<<g, 256>>>(x, NN);
    }
    k_combine<<<12500, 256, SMEM_COMBINE>>>(Wc1, bc1, pH1, NN);

    // ----- conv layer 2: gather only nodes < 8192 -----
    {
        dim3 g(SSED / 16, 3);
        k_gather<<<g, 256>>>(pH1, SSED);
    }
    k_combine<<<2048, 256, SMEM_COMBINE>>>(Wc2, bc2, pH2, SSED);

    // ----- final linear -----
    k_final<<<2048, 256>>>(Wlin, blin, noise);

    // ----- decoder: pred_missing -----
    dim3 g1(2, SSED / 128, 3);    // N=256
    k_tgemm<2><<<g1, 256>>>(pHs, dW1, db1, pZ1, SSED, 256, 64,
                            0, (long)64 * 256, 256, (long)SSED * 256, 256);
    dim3 g2(1, SSED / 64, 3);     // N=32
    k_sgemm<2><<<g2, 256>>>(pZ1, dW2, db2, pZ2, SSED, 32, 256,
                            (long)SSED * 256, (long)256 * 32, 32, (long)SSED * 32, 32);
    k_dw3<<<(3 * SSED + 255) / 256, 256>>>(pZ2, dW3, db3, out);

    // ----- decoder: pred_feat -----
    k_tgemm<1><<<g1, 256>>>(pHs, fW1, fb1, pY1, SSED, 256, 64,
                            0, (long)64 * 256, 256, (long)SSED * 256, 256);
    dim3 g3(16, SSED / 128, 3);   // N=2048
    k_tgemm<1><<<g3, 256>>>(pY1, fW2, fb2, pY2, SSED, 2048, 256,
                            (long)SSED * 256, (long)256 * 2048, 2048,
                            (long)SSED * 2048, 2048);
    dim3 g4(3, SSED / 128, 3);    // N=320
    k_tgemm<3><<<g4, 256>>>(pY2, fW3, fb3, out + 1, SSED, 320, 2048,
                            (long)SSED * 2048, (long)2048 * 320, 320,
                            (long)SSED * 321, 321);
}

// round 6
// speedup vs baseline: 1.4558x; 1.1632x over previous
#include <cuda_runtime.h>
#include <math.h>

#define NN 50000
#define NNP 50048            // padded to multiple of 128
#define EE 800000
#define SSED 8192
#define HD 64

// ---------------- scratch (device globals) ----------------------------------
__device__ int   g_off[3][NN + 1];
__device__ int   g_cur[3 * NN];        // counts, then cursors
__device__ int   g_esrc[3][EE];        // CSR: src indices grouped by dst
__device__ float g_S[NNP * 192];       // [node][r*64+q]; pad rows stay 0
__device__ float g_h1[NNP * HD];
__device__ float g_h2[SSED * HD];
__device__ float g_hs[SSED * HD];
__device__ float g_zd1[3 * SSED * 256];
__device__ float g_zd2[3 * SSED * 32];
__device__ float g_yf1[3 * SSED * 256];
__device__ float g_yf2[3 * SSED * 2048];

// ---------------- CSR construction ------------------------------------------
__global__ void k_zeroi(int* __restrict__ p, int n) {
    int i = blockIdx.x * blockDim.x + threadIdx.x;
    if (i < n) p[i] = 0;
}

__global__ void k_cnt(const int* __restrict__ d0, const int* __restrict__ d1,
                      const int* __restrict__ d2) {
    const int r = blockIdx.y;
    const int* d = (r == 0) ? d0 : ((r == 1) ? d1 : d2);
    int e = blockIdx.x * blockDim.x + threadIdx.x;
    if (e < EE) atomicAdd(&g_cur[r * NN + d[e]], 1);
}

// 3 blocks x 1024 thr: each thread owns 49 counters; serial sum + one ladder
__global__ void k_scan() {
    const int r = blockIdx.x;
    const int tid = threadIdx.x;
    __shared__ int sm[1024];
    const int CH = 49;                       // ceil(50000/1024)
    int t0 = tid * CH;
    int t1 = t0 + CH; if (t1 > NN) t1 = NN;
    int sum = 0;
    for (int i = t0; i < t1; i++) sum += g_cur[r * NN + i];
    sm[tid] = sum;
    __syncthreads();
#pragma unroll
    for (int o = 1; o < 1024; o <<= 1) {
        int v = (tid >= o) ? sm[tid - o] : 0;
        __syncthreads();
        sm[tid] += v;
        __syncthreads();
    }
    int run = sm[tid] - sum;                 // exclusive prefix
    for (int i = t0; i < t1; i++) {
        int c = g_cur[r * NN + i];
        g_off[r][i] = run;
        run += c;
        g_cur[r * NN + i] = 0;               // reset for fill cursors
    }
    if (tid == 1023) g_off[r][NN] = run;
}

__global__ void k_fill(const int* __restrict__ s0, const int* __restrict__ d0,
                       const int* __restrict__ s1, const int* __restrict__ d1,
                       const int* __restrict__ s2, const int* __restrict__ d2) {
    const int r = blockIdx.y;
    const int* s = (r == 0) ? s0 : ((r == 1) ? s1 : s2);
    const int* d = (r == 0) ? d0 : ((r == 1) ? d1 : d2);
    int e = blockIdx.x * blockDim.x + threadIdx.x;
    if (e < EE) {
        int dv = d[e];
        int pos = g_off[r][dv] + atomicAdd(&g_cur[r * NN + dv], 1);
        g_esrc[r][pos] = s[e];
    }
}

// gather: S[node][r*64+q..] = mean of h[src]; 16 thr per node, MLP=4 unroll
__global__ void k_gather(const float* __restrict__ h, int nLimit) {
    const int r = blockIdx.y;
    int node = blockIdx.x * 16 + (threadIdx.x >> 4);
    if (node >= nLimit) return;
    const int q = (threadIdx.x & 15) << 2;
    const int b = g_off[r][node], e2 = g_off[r][node + 1];
    const int* es = g_esrc[r];
    float4 a0 = make_float4(0.f, 0.f, 0.f, 0.f);
    float4 a1 = a0, a2 = a0, a3 = a0;
    int i = b;
    for (; i + 4 <= e2; i += 4) {
        int s0 = __ldg(es + i), s1 = __ldg(es + i + 1);
        int s2 = __ldg(es + i + 2), s3 = __ldg(es + i + 3);
        float4 v0 = *(const float4*)(h + (long)s0 * HD + q);
        float4 v1 = *(const float4*)(h + (long)s1 * HD + q);
        float4 v2 = *(const float4*)(h + (long)s2 * HD + q);
        float4 v3 = *(const float4*)(h + (long)s3 * HD + q);
        a0.x += v0.x; a0.y += v0.y; a0.z += v0.z; a0.w += v0.w;
        a1.x += v1.x; a1.y += v1.y; a1.z += v1.z; a1.w += v1.w;
        a2.x += v2.x; a2.y += v2.y; a2.z += v2.z; a2.w += v2.w;
        a3.x += v3.x; a3.y += v3.y; a3.z += v3.z; a3.w += v3.w;
    }
    for (; i < e2; i++) {
        int s = __ldg(es + i);
        float4 v = *(const float4*)(h + (long)s * HD + q);
        a0.x += v.x; a0.y += v.y; a0.z += v.z; a0.w += v.w;
    }
    a0.x += a1.x + a2.x + a3.x;
    a0.y += a1.y + a2.y + a3.y;
    a0.z += a1.z + a2.z + a3.z;
    a0.w += a1.w + a2.w + a3.w;
    float inv = (e2 > b) ? 1.f / (float)(e2 - b) : 1.f;
    a0.x *= inv; a0.y *= inv; a0.z *= inv; a0.w *= inv;
    *(float4*)(g_S + (long)node * 192 + r * HD + q) = a0;
}

// g_hs = leaky_relu(g_h2 @ Wlin + blin) + noise
__global__ void k_final(const float* __restrict__ W, const float* __restrict__ bias,
                        const float* __restrict__ noise) {
    __shared__ float sW[HD * HD];
    __shared__ float sS[4 * HD];
    for (int i = threadIdx.x; i < HD * HD; i += blockDim.x) sW[i] = W[i];
    __syncthreads();
    const int j = threadIdx.x & 63;
    const int ln = threadIdx.x >> 6;
    for (int n0 = blockIdx.x * 4; n0 < SSED; n0 += gridDim.x * 4) {
        int n = n0 + ln;
        sS[ln * HD + j] = g_h2[(long)n * HD + j];
        __syncthreads();
        float acc = bias[j];
#pragma unroll
        for (int k = 0; k < HD; k++)
            acc = fmaf(sS[ln * HD + k], sW[k * HD + j], acc);
        float v = (acc > 0.f) ? acc : 0.01f * acc;
        g_hs[(long)n * HD + j] = v + noise[(long)n * HD + j];
        __syncthreads();
    }
}

// ---------------- TF32 tensor-core GEMM (256 thr, 64x32 warp tile) ----------
__device__ __forceinline__ void cp16(void* smem, const void* gmem, bool valid) {
    unsigned s = (unsigned)__cvta_generic_to_shared(smem);
    int sz = valid ? 16 : 0;
    asm volatile("cp.async.cg.shared.global [%0], [%1], 16, %2;"
                 :: "r"(s), "l"(gmem), "r"(sz) : "memory");
}
__device__ __forceinline__ unsigned tf32(float f) {
    unsigned u;
    asm("cvt.rna.tf32.f32 %0, %1;" : "=r"(u) : "f"(f));
    return u;
}
__device__ __forceinline__ void mma8(float* c, const unsigned* a, const unsigned* b) {
    asm volatile("mma.sync.aligned.m16n8k8.row.col.f32.tf32.tf32.f32 "
                 "{%0,%1,%2,%3}, {%4,%5,%6,%7}, {%8,%9}, {%0,%1,%2,%3};"
                 : "+f"(c[0]), "+f"(c[1]), "+f"(c[2]), "+f"(c[3])
                 : "r"(a[0]), "r"(a[1]), "r"(a[2]), "r"(a[3]), "r"(b[0]), "r"(b[1]));
}

template <int ACT>   // 1=relu, 2=leaky(0.01), 3=tanh
__global__ void __launch_bounds__(256, 2)
k_tgemm(const float* __restrict__ Aall, const float* __restrict__ Ball,
        const float* __restrict__ biasAll, float* __restrict__ Call,
        int M, int N, int K, long sA, long sB, long sBias, long sC, int ldc) {
    const int r = blockIdx.z;
    const float* A = Aall + (long)r * sA;
    const float* B = Ball + (long)r * sB;
    const float* bias = biasAll + (long)r * sBias;
    float* C = Call + (long)r * sC;

    __shared__ float As[2][128][20];
    __shared__ float Bs[2][16][136];

    const int t = threadIdx.x;
    const int lane = t & 31;
    const int warp = t >> 5;
    const int wm = (warp >> 2) * 64;
    const int wn = (warp & 3) * 32;
    const long bm = (long)blockIdx.y * 128;
    const int bn = blockIdx.x * 128;

    const int aRow = t >> 2;
    const int aCol = (t & 3) << 2;
    const int bRow = t >> 5;
    const int bCol = (t & 31) << 2;
    const bool bValid = (bn + bCol) < N;
    const int bnc = bValid ? bn + bCol : 0;

    const int gid = lane >> 2;
    const int tig = lane & 3;

    float acc[4][4][4];
#pragma unroll
    for (int i = 0; i < 4; i++)
#pragma unroll
        for (int j = 0; j < 4; j++)
#pragma unroll
            for (int c = 0; c < 4; c++) acc[i][j][c] = 0.f;

    const int KT = K / 16;

    {
        cp16(&As[0][aRow][aCol], A + (bm + aRow) * (long)K + aCol, true);
        cp16(&As[0][aRow + 64][aCol], A + (bm + aRow + 64) * (long)K + aCol, true);
        cp16(&Bs[0][bRow][bCol], B + (long)bRow * N + bnc, bValid);
        cp16(&Bs[0][bRow + 8][bCol], B + (long)(bRow + 8) * N + bnc, bValid);
        asm volatile("cp.async.commit_group;" ::: "memory");
        asm volatile("cp.async.wait_group 0;" ::: "memory");
        __syncthreads();
    }

    for (int kt = 0; kt < KT; kt++) {
        const int cb = kt & 1, nb = (kt + 1) & 1;
        if (kt + 1 < KT) {
            long ko = (long)(kt + 1) * 16;
            cp16(&As[nb][aRow][aCol], A + (bm + aRow) * (long)K + ko + aCol, true);
            cp16(&As[nb][aRow + 64][aCol], A + (bm + aRow + 64) * (long)K + ko + aCol, true);
            cp16(&Bs[nb][bRow][bCol], B + (ko + bRow) * (long)N + bnc, bValid);
            cp16(&Bs[nb][bRow + 8][bCol], B + (ko + bRow + 8) * (long)N + bnc, bValid);
            asm volatile("cp.async.commit_group;" ::: "memory");
        }
#pragma unroll
        for (int k8 = 0; k8 < 2; k8++) {
            const int k0 = k8 * 8;
            unsigned a[4][4], b[4][2];
#pragma unroll
            for (int tm = 0; tm < 4; tm++) {
                int m = wm + tm * 16 + gid;
                a[tm][0] = tf32(As[cb][m][k0 + tig]);
                a[tm][1] = tf32(As[cb][m + 8][k0 + tig]);
                a[tm][2] = tf32(As[cb][m][k0 + tig + 4]);
                a[tm][3] = tf32(As[cb][m + 8][k0 + tig + 4]);
            }
#pragma unroll
            for (int tn = 0; tn < 4; tn++) {
                int n = wn + tn * 8 + gid;
                b[tn][0] = tf32(Bs[cb][k0 + tig][n]);
                b[tn][1] = tf32(Bs[cb][k0 + tig + 4][n]);
            }
#pragma unroll
            for (int tm = 0; tm < 4; tm++)
#pragma unroll
                for (int tn = 0; tn < 4; tn++)
                    mma8(acc[tm][tn], a[tm], b[tn]);
        }
        if (kt + 1 < KT)
            asm volatile("cp.async.wait_group 0;" ::: "memory");
        __syncthreads();
    }

#pragma unroll
    for (int tm = 0; tm < 4; tm++) {
        long row0 = bm + wm + tm * 16 + gid;
#pragma unroll
        for (int tn = 0; tn < 4; tn++) {
            int col = bn + wn + tn * 8 + tig * 2;
            if (col < N) {
                float bs0 = bias[col], bs1 = bias[col + 1];
#pragma unroll
                for (int h = 0; h < 2; h++) {
                    long row = row0 + h * 8;
                    float u0 = acc[tm][tn][h * 2 + 0] + bs0;
                    float u1 = acc[tm][tn][h * 2 + 1] + bs1;
                    if (ACT == 1) { u0 = fmaxf(u0, 0.f); u1 = fmaxf(u1, 0.f); }
                    else if (ACT == 2) { u0 = (u0 > 0.f) ? u0 : 0.01f * u0;
                                         u1 = (u1 > 0.f) ? u1 : 0.01f * u1; }
                    else { u0 = tanhf(u0); u1 = tanhf(u1); }
                    C[row * ldc + col] = u0;
                    C[row * ldc + col + 1] = u1;
                }
            }
        }
    }
}

// ---------------- small 64x64 SGEMM (N=32 case) ----------------------------
template <int ACT>
__global__ void k_sgemm(const float* __restrict__ Aall, const float* __restrict__ Ball,
                        const float* __restrict__ biasAll, float* __restrict__ Call,
                        int M, int N, int K,
                        long sA, long sB, long sBias, long sC, int ldc) {
    const int r = blockIdx.z;
    const float* A = Aall + (long)r * sA;
    const float* B = Ball + (long)r * sB;
    const float* bias = biasAll + (long)r * sBias;
    float* C = Call + (long)r * sC;

    __shared__ float As[16][65];
    __shared__ float Bs[16][64];

    const int tid = threadIdx.x;
    const int bm = blockIdx.y * 64;
    const int bn = blockIdx.x * 64;

    const int aRow = tid >> 2;
    const int aCol = (tid & 3) << 2;
    const int bRow = tid >> 4;
    const int bCol = (tid & 15) << 2;

    const int tx = tid & 15;
    const int ty = tid >> 4;

    float acc[4][4];
#pragma unroll
    for (int m = 0; m < 4; m++)
#pragma unroll
        for (int n = 0; n < 4; n++) acc[m][n] = 0.f;

    for (int k0 = 0; k0 < K; k0 += 16) {
        float4 av = *(const float4*)(A + (long)(bm + aRow) * K + k0 + aCol);
        As[aCol + 0][aRow] = av.x;
        As[aCol + 1][aRow] = av.y;
        As[aCol + 2][aRow] = av.z;
        As[aCol + 3][aRow] = av.w;
        if (bn + bCol + 3 < N) {
            *(float4*)(&Bs[bRow][bCol]) =
                *(const float4*)(B + (long)(k0 + bRow) * N + bn + bCol);
        } else {
#pragma unroll
            for (int i2 = 0; i2 < 4; i2++)
                Bs[bRow][bCol + i2] =
                    (bn + bCol + i2 < N) ? B[(long)(k0 + bRow) * N + bn + bCol + i2] : 0.f;
        }
        __syncthreads();
#pragma unroll
        for (int k = 0; k < 16; k++) {
            float a0 = As[k][ty * 4 + 0], a1 = As[k][ty * 4 + 1];
            float a2 = As[k][ty * 4 + 2], a3 = As[k][ty * 4 + 3];
            float b0 = Bs[k][tx * 4 + 0], b1 = Bs[k][tx * 4 + 1];
            float b2 = Bs[k][tx * 4 + 2], b3 = Bs[k][tx * 4 + 3];
            acc[0][0] = fmaf(a0, b0, acc[0][0]); acc[0][1] = fmaf(a0, b1, acc[0][1]);
            acc[0][2] = fmaf(a0, b2, acc[0][2]); acc[0][3] = fmaf(a0, b3, acc[0][3]);
            acc[1][0] = fmaf(a1, b0, acc[1][0]); acc[1][1] = fmaf(a1, b1, acc[1][1]);
            acc[1][2] = fmaf(a1, b2, acc[1][2]); acc[1][3] = fmaf(a1, b3, acc[1][3]);
            acc[2][0] = fmaf(a2, b0, acc[2][0]); acc[2][1] = fmaf(a2, b1, acc[2][1]);
            acc[2][2] = fmaf(a2, b2, acc[2][2]); acc[2][3] = fmaf(a2, b3, acc[2][3]);
            acc[3][0] = fmaf(a3, b0, acc[3][0]); acc[3][1] = fmaf(a3, b1, acc[3][1]);
            acc[3][2] = fmaf(a3, b2, acc[3][2]); acc[3][3] = fmaf(a3, b3, acc[3][3]);
        }
        __syncthreads();
    }
#pragma unroll
    for (int m = 0; m < 4; m++) {
        int row = bm + ty * 4 + m;
#pragma unroll
        for (int n = 0; n < 4; n++) {
            int col = bn + tx * 4 + n;
            if (col < N) {
                float v = acc[m][n] + bias[col];
                if (ACT == 1) v = fmaxf(v, 0.f);
                else if (ACT == 2) v = (v > 0.f) ? v : 0.01f * v;
                else if (ACT == 3) v = tanhf(v);
                C[(long)row * ldc + col] = v;
            }
        }
    }
}

// pred_missing head
__global__ void k_dw3(const float* __restrict__ z, const float* __restrict__ W,
                      const float* __restrict__ b, float* __restrict__ out) {
    int i = blockIdx.x * blockDim.x + threadIdx.x;
    if (i >= 3 * SSED) return;
    int r = i / SSED;
    int s = i % SSED;
    const float* zz = z + ((long)r * SSED + s) * 32;
    const float* w = W + r * 32;
    float acc = b[r];
#pragma unroll
    for (int k = 0; k < 32; k++) acc = fmaf(zz[k], w[k], acc);
    out[((long)r * SSED + s) * 321] = fmaxf(acc, 0.f);
}

// ---------------- host launch ----------------------------------------------
extern "C" void kernel_launch(void* const* d_in, const int* in_sizes, int n_in,
                              void* d_out, int out_size) {
    static const int MAP_DICT[27] = {0,1,2,3,4,5,6,7,8,9,10,11,12,13,14,15,16,17,18,19,20,21,22,23,24,25,26};
    static const int MAP_SIG[27]  = {0,1,20,21,22,23,24,25,26,2,3,4,5,6,7,8,9,10,11,12,13,14,15,16,17,18,19};
    static const int MAP_ALPHA[27]= {26,21,22,23,12,24,13,25,14,0,3,1,4,2,5,6,9,7,10,8,11,15,18,16,19,17,20};
    const int* MAP = MAP_DICT;
    if (n_in >= 3) {
        if (in_sizes[2] == 12288) MAP = MAP_SIG;
        else if (in_sizes[2] == 4096) MAP = MAP_ALPHA;
    }

    const float* x     = (const float*)d_in[MAP[0]];
    const float* noise = (const float*)d_in[MAP[1]];
    const int* src[3]  = {(const int*)d_in[MAP[3]], (const int*)d_in[MAP[5]], (const int*)d_in[MAP[7]]};
    const int* dst[3]  = {(const int*)d_in[MAP[4]], (const int*)d_in[MAP[6]], (const int*)d_in[MAP[8]]};
    const float* Wc1   = (const float*)d_in[MAP[9]];
    const float* bc1   = (const float*)d_in[MAP[10]];
    const float* Wc2   = (const float*)d_in[MAP[11]];
    const float* bc2   = (const float*)d_in[MAP[12]];
    const float* Wlin  = (const float*)d_in[MAP[13]];
    const float* blin  = (const float*)d_in[MAP[14]];
    const float* dW1   = (const float*)d_in[MAP[15]];
    const float* db1   = (const float*)d_in[MAP[16]];
    const float* dW2   = (const float*)d_in[MAP[17]];
    const float* db2   = (const float*)d_in[MAP[18]];
    const float* dW3   = (const float*)d_in[MAP[19]];
    const float* db3   = (const float*)d_in[MAP[20]];
    const float* fW1   = (const float*)d_in[MAP[21]];
    const float* fb1   = (const float*)d_in[MAP[22]];
    const float* fW2   = (const float*)d_in[MAP[23]];
    const float* fb2   = (const float*)d_in[MAP[24]];
    const float* fW3   = (const float*)d_in[MAP[25]];
    const float* fb3   = (const float*)d_in[MAP[26]];
    float* out = (float*)d_out;

    int* pCur;
    float *pS, *pH1, *pH2, *pHs, *pZ1, *pZ2, *pY1, *pY2;
    cudaGetSymbolAddress((void**)&pCur, g_cur);
    cudaGetSymbolAddress((void**)&pS,   g_S);
    cudaGetSymbolAddress((void**)&pH1,  g_h1);
    cudaGetSymbolAddress((void**)&pH2,  g_h2);
    cudaGetSymbolAddress((void**)&pHs,  g_hs);
    cudaGetSymbolAddress((void**)&pZ1,  g_zd1);
    cudaGetSymbolAddress((void**)&pZ2,  g_zd2);
    cudaGetSymbolAddress((void**)&pY1,  g_yf1);
    cudaGetSymbolAddress((void**)&pY2,  g_yf2);

    // ----- CSR build (counts -> scan -> fill) -----
    k_zeroi<<<(3 * NN + 255) / 256, 256>>>(pCur, 3 * NN);
    {
        dim3 g((EE + 255) / 256, 3);
        k_cnt<<<g, 256>>>(dst[0], dst[1], dst[2]);
        k_scan<<<3, 1024>>>();
        k_fill<<<g, 256>>>(src[0], dst[0], src[1], dst[1], src[2], dst[2]);
    }

    // ----- conv layer 1: gather (S layout [node][192]) + GEMM combine -----
    {
        dim3 g((NN + 15) / 16, 3);
        k_gather<<<g, 256>>>(x, NN);
    }
    k_tgemm<1><<<dim3(1, NNP / 128, 1), 256>>>(pS, Wc1, bc1, pH1,
                                               NNP, 64, 192, 0, 0, 0, 0, 64);

    // ----- conv layer 2: gather only nodes < 8192 + GEMM combine -----
    {
        dim3 g(SSED / 16, 3);
        k_gather<<<g, 256>>>(pH1, SSED);
    }
    k_tgemm<1><<<dim3(1, SSED / 128, 1), 256>>>(pS, Wc2, bc2, pH2,
                                                SSED, 64, 192, 0, 0, 0, 0, 64);

    // ----- final linear -----
    k_final<<<2048, 256>>>(Wlin, blin, noise);

    // ----- decoder: pred_missing -----
    dim3 g1(2, SSED / 128, 3);    // N=256
    k_tgemm<2><<<g1, 256>>>(pHs, dW1, db1, pZ1, SSED, 256, 64,
                            0, (long)64 * 256, 256, (long)SSED * 256, 256);
    dim3 g2(1, SSED / 64, 3);     // N=32
    k_sgemm<2><<<g2, 256>>>(pZ1, dW2, db2, pZ2, SSED, 32, 256,
                            (long)SSED * 256, (long)256 * 32, 32, (long)SSED * 32, 32);
    k_dw3<<<(3 * SSED + 255) / 256, 256>>>(pZ2, dW3, db3, out);

    // ----- decoder: pred_feat -----
    k_tgemm<1><<<g1, 256>>>(pHs, fW1, fb1, pY1, SSED, 256, 64,
                            0, (long)64 * 256, 256, (long)SSED * 256, 256);
    dim3 g3(16, SSED / 128, 3);   // N=2048
    k_tgemm<1><<<g3, 256>>>(pY1, fW2, fb2, pY2, SSED, 2048, 256,
                            (long)SSED * 256, (long)256 * 2048, 2048,
                            (long)SSED * 2048, 2048);
    dim3 g4(3, SSED / 128, 3);    // N=320
    k_tgemm<3><<<g4, 256>>>(pY2, fW3, fb3, out + 1, SSED, 320, 2048,
                            (long)SSED * 2048, (long)2048 * 320, 320,
                            (long)SSED * 321, 321);
}

// round 7
// speedup vs baseline: 2.1104x; 1.4496x over previous
#include <cuda_runtime.h>
#include <cuda_fp16.h>
#include <math.h>

#define NN 50000
#define NNP 50048            // padded to multiple of 128
#define EE 800000
#define SSED 8192
#define HD 64

// ---------------- scratch (device globals) ----------------------------------
__device__ int    g_off[3][NN + 1];
__device__ int    g_cur[3 * NN];
__device__ int    g_esrc[3][EE];
__device__ float  g_S[NNP * 192];       // [node][r*64+q]; pad rows stay 0
__device__ float  g_h1[NNP * HD];
__device__ float  g_h2[SSED * HD];
__device__ __half g_hsh[SSED * HD];     // seed embedding, fp16
__device__ float  g_zd1[3 * SSED * 256];
__device__ float  g_zd2[3 * SSED * 32];
__device__ __half g_y1h[3 * SSED * 256];
__device__ __half g_y2h[3 * SSED * 2048];
__device__ __half g_wd1h[3 * 64 * 256];
__device__ __half g_wf1h[3 * 64 * 256];
__device__ __half g_wf2h[3 * 256 * 2048];
__device__ __half g_wf3h[3 * 2048 * 320];

// ---------------- CSR construction ------------------------------------------
__global__ void k_zeroi(int* __restrict__ p, int n) {
    int i = blockIdx.x * blockDim.x + threadIdx.x;
    if (i < n) p[i] = 0;
}

__global__ void k_cnt(const int* __restrict__ d0, const int* __restrict__ d1,
                      const int* __restrict__ d2) {
    const int r = blockIdx.y;
    const int* d = (r == 0) ? d0 : ((r == 1) ? d1 : d2);
    int e = blockIdx.x * blockDim.x + threadIdx.x;
    if (e < EE) atomicAdd(&g_cur[r * NN + d[e]], 1);
}

__global__ void k_scan() {
    const int r = blockIdx.x;
    const int tid = threadIdx.x;
    __shared__ int sm[1024];
    const int CH = 49;
    int t0 = tid * CH;
    int t1 = t0 + CH; if (t1 > NN) t1 = NN;
    int sum = 0;
    for (int i = t0; i < t1; i++) sum += g_cur[r * NN + i];
    sm[tid] = sum;
    __syncthreads();
#pragma unroll
    for (int o = 1; o < 1024; o <<= 1) {
        int v = (tid >= o) ? sm[tid - o] : 0;
        __syncthreads();
        sm[tid] += v;
        __syncthreads();
    }
    int run = sm[tid] - sum;
    for (int i = t0; i < t1; i++) {
        int c = g_cur[r * NN + i];
        g_off[r][i] = run;
        run += c;
        g_cur[r * NN + i] = 0;
    }
    if (tid == 1023) g_off[r][NN] = run;
}

__global__ void k_fill(const int* __restrict__ s0, const int* __restrict__ d0,
                       const int* __restrict__ s1, const int* __restrict__ d1,
                       const int* __restrict__ s2, const int* __restrict__ d2) {
    const int r = blockIdx.y;
    const int* s = (r == 0) ? s0 : ((r == 1) ? s1 : s2);
    const int* d = (r == 0) ? d0 : ((r == 1) ? d1 : d2);
    int e = blockIdx.x * blockDim.x + threadIdx.x;
    if (e < EE) {
        int dv = d[e];
        int pos = g_off[r][dv] + atomicAdd(&g_cur[r * NN + dv], 1);
        g_esrc[r][pos] = s[e];
    }
}

// gather: S[node][r*64+q..] = mean of h[src]; 16 thr per node, MLP=4 unroll
__global__ void k_gather(const float* __restrict__ h, int nLimit) {
    const int r = blockIdx.y;
    int node = blockIdx.x * 16 + (threadIdx.x >> 4);
    if (node >= nLimit) return;
    const int q = (threadIdx.x & 15) << 2;
    const int b = g_off[r][node], e2 = g_off[r][node + 1];
    const int* es = g_esrc[r];
    float4 a0 = make_float4(0.f, 0.f, 0.f, 0.f);
    float4 a1 = a0, a2 = a0, a3 = a0;
    int i = b;
    for (; i + 4 <= e2; i += 4) {
        int s0 = __ldg(es + i), s1 = __ldg(es + i + 1);
        int s2 = __ldg(es + i + 2), s3 = __ldg(es + i + 3);
        float4 v0 = *(const float4*)(h + (long)s0 * HD + q);
        float4 v1 = *(const float4*)(h + (long)s1 * HD + q);
        float4 v2 = *(const float4*)(h + (long)s2 * HD + q);
        float4 v3 = *(const float4*)(h + (long)s3 * HD + q);
        a0.x += v0.x; a0.y += v0.y; a0.z += v0.z; a0.w += v0.w;
        a1.x += v1.x; a1.y += v1.y; a1.z += v1.z; a1.w += v1.w;
        a2.x += v2.x; a2.y += v2.y; a2.z += v2.z; a2.w += v2.w;
        a3.x += v3.x; a3.y += v3.y; a3.z += v3.z; a3.w += v3.w;
    }
    for (; i < e2; i++) {
        int s = __ldg(es + i);
        float4 v = *(const float4*)(h + (long)s * HD + q);
        a0.x += v.x; a0.y += v.y; a0.z += v.z; a0.w += v.w;
    }
    a0.x += a1.x + a2.x + a3.x;
    a0.y += a1.y + a2.y + a3.y;
    a0.z += a1.z + a2.z + a3.z;
    a0.w += a1.w + a2.w + a3.w;
    float inv = (e2 > b) ? 1.f / (float)(e2 - b) : 1.f;
    a0.x *= inv; a0.y *= inv; a0.z *= inv; a0.w *= inv;
    *(float4*)(g_S + (long)node * 192 + r * HD + q) = a0;
}

// g_hsh = fp16(leaky_relu(g_h2 @ Wlin + blin) + noise)
__global__ void k_final(const float* __restrict__ W, const float* __restrict__ bias,
                        const float* __restrict__ noise) {
    __shared__ float sW[HD * HD];
    __shared__ float sS[4 * HD];
    for (int i = threadIdx.x; i < HD * HD; i += blockDim.x) sW[i] = W[i];
    __syncthreads();
    const int j = threadIdx.x & 63;
    const int ln = threadIdx.x >> 6;
    for (int n0 = blockIdx.x * 4; n0 < SSED; n0 += gridDim.x * 4) {
        int n = n0 + ln;
        sS[ln * HD + j] = g_h2[(long)n * HD + j];
        __syncthreads();
        float acc = bias[j];
#pragma unroll
        for (int k = 0; k < HD; k++)
            acc = fmaf(sS[ln * HD + k], sW[k * HD + j], acc);
        float v = (acc > 0.f) ? acc : 0.01f * acc;
        g_hsh[(long)n * HD + j] = __float2half_rn(v + noise[(long)n * HD + j]);
        __syncthreads();
    }
}

// float -> half converter
__global__ void k_h(const float* __restrict__ s, __half* __restrict__ d, int n) {
    int i = blockIdx.x * blockDim.x + threadIdx.x;
    if (i < n) d[i] = __float2half_rn(s[i]);
}

// ---------------- common asm helpers ----------------------------------------
__device__ __forceinline__ void cp16(void* smem, const void* gmem, bool valid) {
    unsigned s = (unsigned)__cvta_generic_to_shared(smem);
    int sz = valid ? 16 : 0;
    asm volatile("cp.async.cg.shared.global [%0], [%1], 16, %2;"
                 :: "r"(s), "l"(gmem), "r"(sz) : "memory");
}
__device__ __forceinline__ unsigned tf32(float f) {
    unsigned u;
    asm("cvt.rna.tf32.f32 %0, %1;" : "=r"(u) : "f"(f));
    return u;
}
__device__ __forceinline__ void mma8(float* c, const unsigned* a, const unsigned* b) {
    asm volatile("mma.sync.aligned.m16n8k8.row.col.f32.tf32.tf32.f32 "
                 "{%0,%1,%2,%3}, {%4,%5,%6,%7}, {%8,%9}, {%0,%1,%2,%3};"
                 : "+f"(c[0]), "+f"(c[1]), "+f"(c[2]), "+f"(c[3])
                 : "r"(a[0]), "r"(a[1]), "r"(a[2]), "r"(a[3]), "r"(b[0]), "r"(b[1]));
}
__device__ __forceinline__ void mma16h(float* c, const unsigned* a, const unsigned* b) {
    asm volatile("mma.sync.aligned.m16n8k16.row.col.f32.f16.f16.f32 "
                 "{%0,%1,%2,%3}, {%4,%5,%6,%7}, {%8,%9}, {%0,%1,%2,%3};"
                 : "+f"(c[0]), "+f"(c[1]), "+f"(c[2]), "+f"(c[3])
                 : "r"(a[0]), "r"(a[1]), "r"(a[2]), "r"(a[3]), "r"(b[0]), "r"(b[1]));
}
__device__ __forceinline__ void ldsm_x4(unsigned& r0, unsigned& r1, unsigned& r2,
                                        unsigned& r3, const void* p) {
    unsigned a = (unsigned)__cvta_generic_to_shared(p);
    asm volatile("ldmatrix.sync.aligned.m8n8.x4.shared.b16 {%0,%1,%2,%3}, [%4];"
                 : "=r"(r0), "=r"(r1), "=r"(r2), "=r"(r3) : "r"(a));
}
__device__ __forceinline__ void ldsm_x2t(unsigned& r0, unsigned& r1, const void* p) {
    unsigned a = (unsigned)__cvta_generic_to_shared(p);
    asm volatile("ldmatrix.sync.aligned.m8n8.x2.trans.shared.b16 {%0,%1}, [%2];"
                 : "=r"(r0), "=r"(r1) : "r"(a));
}

// ---------------- fp16 tensor-core GEMM (128x128 CTA, 64x32 warp, BK=32) ----
// A: MxK half row-major, B: KxN half row-major. M%128==0, K%32==0, N%16==0.
// ACT: 1=relu, 2=leaky, 3=tanh.  HOUT: 1 -> half output, 0 -> float output.
template <int ACT, int HOUT>
__global__ void __launch_bounds__(256, 2)
k_hgemm(const __half* __restrict__ Aall, const __half* __restrict__ Ball,
        const float* __restrict__ biasAll, void* __restrict__ Call,
        int M, int N, int K, long sA, long sB, long sBias, long sC, int ldc) {
    const int r = blockIdx.z;
    const __half* A = Aall + (long)r * sA;
    const __half* B = Ball + (long)r * sB;
    const float* bias = biasAll + (long)r * sBias;

    __shared__ __half As[2][128][40];    // stride 40 halves = 20 words: LDSM ok
    __shared__ __half Bs[2][32][136];    // stride 136 halves = 68 words: LDSM ok

    const int t = threadIdx.x;
    const int lane = t & 31;
    const int warp = t >> 5;
    const int wm = (warp >> 2) * 64;
    const int wn = (warp & 3) * 32;
    const long bm = (long)blockIdx.y * 128;
    const int bn = blockIdx.x * 128;

    // A tile: 128 rows x 32 halves; thread t -> row t>>1, cols (t&1)*16 + {0,8}
    const int aRow = t >> 1;
    const int aCol = (t & 1) << 4;
    // B tile: 32 rows x 128 halves; thread t -> row t>>3, cols (t&7)*16 + {0,8}
    const int bRow = t >> 3;
    const int bCol = (t & 7) << 4;
    const bool bv0 = (bn + bCol) < N;
    const bool bv1 = (bn + bCol + 8) < N;
    const int bc0 = bv0 ? bn + bCol : 0;
    const int bc1 = bv1 ? bn + bCol + 8 : 0;

    const int gid = lane >> 2;
    const int tig = lane & 3;

    float acc[4][4][4];
#pragma unroll
    for (int i = 0; i < 4; i++)
#pragma unroll
        for (int j = 0; j < 4; j++)
#pragma unroll
            for (int c = 0; c < 4; c++) acc[i][j][c] = 0.f;

    const int KT = K / 32;

    {
        cp16(&As[0][aRow][aCol], A + (bm + aRow) * (long)K + aCol, true);
        cp16(&As[0][aRow][aCol + 8], A + (bm + aRow) * (long)K + aCol + 8, true);
        cp16(&Bs[0][bRow][bCol], B + (long)bRow * N + bc0, bv0);
        cp16(&Bs[0][bRow][bCol + 8], B + (long)bRow * N + bc1, bv1);
        asm volatile("cp.async.commit_group;" ::: "memory");
        asm volatile("cp.async.wait_group 0;" ::: "memory");
        __syncthreads();
    }

    const int aFragRow = lane & 15;
    const int aFragCol = (lane >> 4) << 3;

    for (int kt = 0; kt < KT; kt++) {
        const int cb = kt & 1, nb = (kt + 1) & 1;
        if (kt + 1 < KT) {
            long ko = (long)(kt + 1) * 32;
            cp16(&As[nb][aRow][aCol], A + (bm + aRow) * (long)K + ko + aCol, true);
            cp16(&As[nb][aRow][aCol + 8], A + (bm + aRow) * (long)K + ko + aCol + 8, true);
            cp16(&Bs[nb][bRow][bCol], B + (ko + bRow) * (long)N + bc0, bv0);
            cp16(&Bs[nb][bRow][bCol + 8], B + (ko + bRow) * (long)N + bc1, bv1);
            asm volatile("cp.async.commit_group;" ::: "memory");
        }
#pragma unroll
        for (int kk = 0; kk < 2; kk++) {
            const int k0 = kk * 16;
            unsigned a[4][4], b[4][2];
#pragma unroll
            for (int tm = 0; tm < 4; tm++)
                ldsm_x4(a[tm][0], a[tm][1], a[tm][2], a[tm][3],
                        &As[cb][wm + tm * 16 + aFragRow][k0 + aFragCol]);
#pragma unroll
            for (int tn = 0; tn < 4; tn++)
                ldsm_x2t(b[tn][0], b[tn][1],
                         &Bs[cb][k0 + (lane & 15)][wn + tn * 8]);
#pragma unroll
            for (int tm = 0; tm < 4; tm++)
#pragma unroll
                for (int tn = 0; tn < 4; tn++)
                    mma16h(acc[tm][tn], a[tm], b[tn]);
        }
        if (kt + 1 < KT)
            asm volatile("cp.async.wait_group 0;" ::: "memory");
        __syncthreads();
    }

#pragma unroll
    for (int tm = 0; tm < 4; tm++) {
        long row0 = bm + wm + tm * 16 + gid;
#pragma unroll
        for (int tn = 0; tn < 4; tn++) {
            int col = bn + wn + tn * 8 + tig * 2;
            if (col < N) {
                float bs0 = bias[col], bs1 = bias[col + 1];
#pragma unroll
                for (int h = 0; h < 2; h++) {
                    long row = row0 + h * 8;
                    float u0 = acc[tm][tn][h * 2 + 0] + bs0;
                    float u1 = acc[tm][tn][h * 2 + 1] + bs1;
                    if (ACT == 1) { u0 = fmaxf(u0, 0.f); u1 = fmaxf(u1, 0.f); }
                    else if (ACT == 2) { u0 = (u0 > 0.f) ? u0 : 0.01f * u0;
                                         u1 = (u1 > 0.f) ? u1 : 0.01f * u1; }
                    else { u0 = tanhf(u0); u1 = tanhf(u1); }
                    if (HOUT) {
                        __half* C = (__half*)Call + (long)r * sC;
                        *(__half2*)(C + row * ldc + col) = __floats2half2_rn(u0, u1);
                    } else {
                        float* C = (float*)Call + (long)r * sC;
                        C[row * ldc + col] = u0;
                        C[row * ldc + col + 1] = u1;
                    }
                }
            }
        }
    }
}

// ---------------- TF32 tensor-core GEMM (for fp32 conv combines) ------------
template <int ACT>
__global__ void __launch_bounds__(256, 2)
k_tgemm(const float* __restrict__ Aall, const float* __restrict__ Ball,
        const float* __restrict__ biasAll, float* __restrict__ Call,
        int M, int N, int K, long sA, long sB, long sBias, long sC, int ldc) {
    const int r = blockIdx.z;
    const float* A = Aall + (long)r * sA;
    const float* B = Ball + (long)r * sB;
    const float* bias = biasAll + (long)r * sBias;
    float* C = Call + (long)r * sC;

    __shared__ float As[2][128][20];
    __shared__ float Bs[2][16][136];

    const int t = threadIdx.x;
    const int lane = t & 31;
    const int warp = t >> 5;
    const int wm = (warp >> 2) * 64;
    const int wn = (warp & 3) * 32;
    const long bm = (long)blockIdx.y * 128;
    const int bn = blockIdx.x * 128;

    const int aRow = t >> 2;
    const int aCol = (t & 3) << 2;
    const int bRow = t >> 5;
    const int bCol = (t & 31) << 2;
    const bool bValid = (bn + bCol) < N;
    const int bnc = bValid ? bn + bCol : 0;

    const int gid = lane >> 2;
    const int tig = lane & 3;

    float acc[4][4][4];
#pragma unroll
    for (int i = 0; i < 4; i++)
#pragma unroll
        for (int j = 0; j < 4; j++)
#pragma unroll
            for (int c = 0; c < 4; c++) acc[i][j][c] = 0.f;

    const int KT = K / 16;

    {
        cp16(&As[0][aRow][aCol], A + (bm + aRow) * (long)K + aCol, true);
        cp16(&As[0][aRow + 64][aCol], A + (bm + aRow + 64) * (long)K + aCol, true);
        cp16(&Bs[0][bRow][bCol], B + (long)bRow * N + bnc, bValid);
        cp16(&Bs[0][bRow + 8][bCol], B + (long)(bRow + 8) * N + bnc, bValid);
        asm volatile("cp.async.commit_group;" ::: "memory");
        asm volatile("cp.async.wait_group 0;" ::: "memory");
        __syncthreads();
    }

    for (int kt = 0; kt < KT; kt++) {
        const int cb = kt & 1, nb = (kt + 1) & 1;
        if (kt + 1 < KT) {
            long ko = (long)(kt + 1) * 16;
            cp16(&As[nb][aRow][aCol], A + (bm + aRow) * (long)K + ko + aCol, true);
            cp16(&As[nb][aRow + 64][aCol], A + (bm + aRow + 64) * (long)K + ko + aCol, true);
            cp16(&Bs[nb][bRow][bCol], B + (ko + bRow) * (long)N + bnc, bValid);
            cp16(&Bs[nb][bRow + 8][bCol], B + (ko + bRow + 8) * (long)N + bnc, bValid);
            asm volatile("cp.async.commit_group;" ::: "memory");
        }
#pragma unroll
        for (int k8 = 0; k8 < 2; k8++) {
            const int k0 = k8 * 8;
            unsigned a[4][4], b[4][2];
#pragma unroll
            for (int tm = 0; tm < 4; tm++) {
                int m = wm + tm * 16 + gid;
                a[tm][0] = tf32(As[cb][m][k0 + tig]);
                a[tm][1] = tf32(As[cb][m + 8][k0 + tig]);
                a[tm][2] = tf32(As[cb][m][k0 + tig + 4]);
                a[tm][3] = tf32(As[cb][m + 8][k0 + tig + 4]);
            }
#pragma unroll
            for (int tn = 0; tn < 4; tn++) {
                int n = wn + tn * 8 + gid;
                b[tn][0] = tf32(Bs[cb][k0 + tig][n]);
                b[tn][1] = tf32(Bs[cb][k0 + tig + 4][n]);
            }
#pragma unroll
            for (int tm = 0; tm < 4; tm++)
#pragma unroll
                for (int tn = 0; tn < 4; tn++)
                    mma8(acc[tm][tn], a[tm], b[tn]);
        }
        if (kt + 1 < KT)
            asm volatile("cp.async.wait_group 0;" ::: "memory");
        __syncthreads();
    }

#pragma unroll
    for (int tm = 0; tm < 4; tm++) {
        long row0 = bm + wm + tm * 16 + gid;
#pragma unroll
        for (int tn = 0; tn < 4; tn++) {
            int col = bn + wn + tn * 8 + tig * 2;
            if (col < N) {
                float bs0 = bias[col], bs1 = bias[col + 1];
#pragma unroll
                for (int h = 0; h < 2; h++) {
                    long row = row0 + h * 8;
                    float u0 = acc[tm][tn][h * 2 + 0] + bs0;
                    float u1 = acc[tm][tn][h * 2 + 1] + bs1;
                    if (ACT == 1) { u0 = fmaxf(u0, 0.f); u1 = fmaxf(u1, 0.f); }
                    else if (ACT == 2) { u0 = (u0 > 0.f) ? u0 : 0.01f * u0;
                                         u1 = (u1 > 0.f) ? u1 : 0.01f * u1; }
                    else { u0 = tanhf(u0); u1 = tanhf(u1); }
                    C[row * ldc + col] = u0;
                    C[row * ldc + col + 1] = u1;
                }
            }
        }
    }
}

// ---------------- small 64x64 SGEMM (N=32 case) ----------------------------
template <int ACT>
__global__ void k_sgemm(const float* __restrict__ Aall, const float* __restrict__ Ball,
                        const float* __restrict__ biasAll, float* __restrict__ Call,
                        int M, int N, int K,
                        long sA, long sB, long sBias, long sC, int ldc) {
    const int r = blockIdx.z;
    const float* A = Aall + (long)r * sA;
    const float* B = Ball + (long)r * sB;
    const float* bias = biasAll + (long)r * sBias;
    float* C = Call + (long)r * sC;

    __shared__ float As[16][65];
    __shared__ float Bs[16][64];

    const int tid = threadIdx.x;
    const int bm = blockIdx.y * 64;
    const int bn = blockIdx.x * 64;

    const int aRow = tid >> 2;
    const int aCol = (tid & 3) << 2;
    const int bRow = tid >> 4;
    const int bCol = (tid & 15) << 2;

    const int tx = tid & 15;
    const int ty = tid >> 4;

    float acc[4][4];
#pragma unroll
    for (int m = 0; m < 4; m++)
#pragma unroll
        for (int n = 0; n < 4; n++) acc[m][n] = 0.f;

    for (int k0 = 0; k0 < K; k0 += 16) {
        float4 av = *(const float4*)(A + (long)(bm + aRow) * K + k0 + aCol);
        As[aCol + 0][aRow] = av.x;
        As[aCol + 1][aRow] = av.y;
        As[aCol + 2][aRow] = av.z;
        As[aCol + 3][aRow] = av.w;
        if (bn + bCol + 3 < N) {
            *(float4*)(&Bs[bRow][bCol]) =
                *(const float4*)(B + (long)(k0 + bRow) * N + bn + bCol);
        } else {
#pragma unroll
            for (int i2 = 0; i2 < 4; i2++)
                Bs[bRow][bCol + i2] =
                    (bn + bCol + i2 < N) ? B[(long)(k0 + bRow) * N + bn + bCol + i2] : 0.f;
        }
        __syncthreads();
#pragma unroll
        for (int k = 0; k < 16; k++) {
            float a0 = As[k][ty * 4 + 0], a1 = As[k][ty * 4 + 1];
            float a2 = As[k][ty * 4 + 2], a3 = As[k][ty * 4 + 3];
            float b0 = Bs[k][tx * 4 + 0], b1 = Bs[k][tx * 4 + 1];
            float b2 = Bs[k][tx * 4 + 2], b3 = Bs[k][tx * 4 + 3];
            acc[0][0] = fmaf(a0, b0, acc[0][0]); acc[0][1] = fmaf(a0, b1, acc[0][1]);
            acc[0][2] = fmaf(a0, b2, acc[0][2]); acc[0][3] = fmaf(a0, b3, acc[0][3]);
            acc[1][0] = fmaf(a1, b0, acc[1][0]); acc[1][1] = fmaf(a1, b1, acc[1][1]);
            acc[1][2] = fmaf(a1, b2, acc[1][2]); acc[1][3] = fmaf(a1, b3, acc[1][3]);
            acc[2][0] = fmaf(a2, b0, acc[2][0]); acc[2][1] = fmaf(a2, b1, acc[2][1]);
            acc[2][2] = fmaf(a2, b2, acc[2][2]); acc[2][3] = fmaf(a2, b3, acc[2][3]);
            acc[3][0] = fmaf(a3, b0, acc[3][0]); acc[3][1] = fmaf(a3, b1, acc[3][1]);
            acc[3][2] = fmaf(a3, b2, acc[3][2]); acc[3][3] = fmaf(a3, b3, acc[3][3]);
        }
        __syncthreads();
    }
#pragma unroll
    for (int m = 0; m < 4; m++) {
        int row = bm + ty * 4 + m;
#pragma unroll
        for (int n = 0; n < 4; n++) {
            int col = bn + tx * 4 + n;
            if (col < N) {
                float v = acc[m][n] + bias[col];
                if (ACT == 1) v = fmaxf(v, 0.f);
                else if (ACT == 2) v = (v > 0.f) ? v : 0.01f * v;
                else if (ACT == 3) v = tanhf(v);
                C[(long)row * ldc + col] = v;
            }
        }
    }
}

// pred_missing head
__global__ void k_dw3(const float* __restrict__ z, const float* __restrict__ W,
                      const float* __restrict__ b, float* __restrict__ out) {
    int i = blockIdx.x * blockDim.x + threadIdx.x;
    if (i >= 3 * SSED) return;
    int r = i / SSED;
    int s = i % SSED;
    const float* zz = z + ((long)r * SSED + s) * 32;
    const float* w = W + r * 32;
    float acc = b[r];
#pragma unroll
    for (int k = 0; k < 32; k++) acc = fmaf(zz[k], w[k], acc);
    out[((long)r * SSED + s) * 321] = fmaxf(acc, 0.f);
}

// ---------------- host launch ----------------------------------------------
extern "C" void kernel_launch(void* const* d_in, const int* in_sizes, int n_in,
                              void* d_out, int out_size) {
    static const int MAP_DICT[27] = {0,1,2,3,4,5,6,7,8,9,10,11,12,13,14,15,16,17,18,19,20,21,22,23,24,25,26};
    static const int MAP_SIG[27]  = {0,1,20,21,22,23,24,25,26,2,3,4,5,6,7,8,9,10,11,12,13,14,15,16,17,18,19};
    static const int MAP_ALPHA[27]= {26,21,22,23,12,24,13,25,14,0,3,1,4,2,5,6,9,7,10,8,11,15,18,16,19,17,20};
    const int* MAP = MAP_DICT;
    if (n_in >= 3) {
        if (in_sizes[2] == 12288) MAP = MAP_SIG;
        else if (in_sizes[2] == 4096) MAP = MAP_ALPHA;
    }

    const float* x     = (const float*)d_in[MAP[0]];
    const float* noise = (const float*)d_in[MAP[1]];
    const int* src[3]  = {(const int*)d_in[MAP[3]], (const int*)d_in[MAP[5]], (const int*)d_in[MAP[7]]};
    const int* dst[3]  = {(const int*)d_in[MAP[4]], (const int*)d_in[MAP[6]], (const int*)d_in[MAP[8]]};
    const float* Wc1   = (const float*)d_in[MAP[9]];
    const float* bc1   = (const float*)d_in[MAP[10]];
    const float* Wc2   = (const float*)d_in[MAP[11]];
    const float* bc2   = (const float*)d_in[MAP[12]];
    const float* Wlin  = (const float*)d_in[MAP[13]];
    const float* blin  = (const float*)d_in[MAP[14]];
    const float* dW1   = (const float*)d_in[MAP[15]];
    const float* db1   = (const float*)d_in[MAP[16]];
    const float* dW2   = (const float*)d_in[MAP[17]];
    const float* db2   = (const float*)d_in[MAP[18]];
    const float* dW3   = (const float*)d_in[MAP[19]];
    const float* db3   = (const float*)d_in[MAP[20]];
    const float* fW1   = (const float*)d_in[MAP[21]];
    const float* fb1   = (const float*)d_in[MAP[22]];
    const float* fW2   = (const float*)d_in[MAP[23]];
    const float* fb2   = (const float*)d_in[MAP[24]];
    const float* fW3   = (const float*)d_in[MAP[25]];
    const float* fb3   = (const float*)d_in[MAP[26]];
    float* out = (float*)d_out;

    int* pCur;
    float *pS, *pH1, *pH2, *pZ1, *pZ2;
    __half *pHsh, *pY1h, *pY2h, *pWd1h, *pWf1h, *pWf2h, *pWf3h;
    cudaGetSymbolAddress((void**)&pCur,  g_cur);
    cudaGetSymbolAddress((void**)&pS,    g_S);
    cudaGetSymbolAddress((void**)&pH1,   g_h1);
    cudaGetSymbolAddress((void**)&pH2,   g_h2);
    cudaGetSymbolAddress((void**)&pHsh,  g_hsh);
    cudaGetSymbolAddress((void**)&pZ1,   g_zd1);
    cudaGetSymbolAddress((void**)&pZ2,   g_zd2);
    cudaGetSymbolAddress((void**)&pY1h,  g_y1h);
    cudaGetSymbolAddress((void**)&pY2h,  g_y2h);
    cudaGetSymbolAddress((void**)&pWd1h, g_wd1h);
    cudaGetSymbolAddress((void**)&pWf1h, g_wf1h);
    cudaGetSymbolAddress((void**)&pWf2h, g_wf2h);
    cudaGetSymbolAddress((void**)&pWf3h, g_wf3h);

    // ----- weight conversion (independent of graph work) -----
    k_h<<<(3 * 64 * 256 + 255) / 256, 256>>>(dW1, pWd1h, 3 * 64 * 256);
    k_h<<<(3 * 64 * 256 + 255) / 256, 256>>>(fW1, pWf1h, 3 * 64 * 256);
    k_h<<<(3 * 256 * 2048 + 255) / 256, 256>>>(fW2, pWf2h, 3 * 256 * 2048);
    k_h<<<(3 * 2048 * 320 + 255) / 256, 256>>>(fW3, pWf3h, 3 * 2048 * 320);

    // ----- CSR build -----
    k_zeroi<<<(3 * NN + 255) / 256, 256>>>(pCur, 3 * NN);
    {
        dim3 g((EE + 255) / 256, 3);
        k_cnt<<<g, 256>>>(dst[0], dst[1], dst[2]);
        k_scan<<<3, 1024>>>();
        k_fill<<<g, 256>>>(src[0], dst[0], src[1], dst[1], src[2], dst[2]);
    }

    // ----- conv layer 1 -----
    {
        dim3 g((NN + 15) / 16, 3);
        k_gather<<<g, 256>>>(x, NN);
    }
    k_tgemm<1><<<dim3(1, NNP / 128, 1), 256>>>(pS, Wc1, bc1, pH1,
                                               NNP, 64, 192, 0, 0, 0, 0, 64);

    // ----- conv layer 2 -----
    {
        dim3 g(SSED / 16, 3);
        k_gather<<<g, 256>>>(pH1, SSED);
    }
    k_tgemm<1><<<dim3(1, SSED / 128, 1), 256>>>(pS, Wc2, bc2, pH2,
                                                SSED, 64, 192, 0, 0, 0, 0, 64);

    // ----- final linear (writes fp16 hs) -----
    k_final<<<2048, 256>>>(Wlin, blin, noise);

    // ----- decoder: pred_missing -----
    dim3 g1(2, SSED / 128, 3);    // N=256
    k_hgemm<2, 0><<<g1, 256>>>(pHsh, pWd1h, db1, pZ1, SSED, 256, 64,
                               0, (long)64 * 256, 256, (long)SSED * 256, 256);
    dim3 g2(1, SSED / 64, 3);     // N=32
    k_sgemm<2><<<g2, 256>>>(pZ1, dW2, db2, pZ2, SSED, 32, 256,
                            (long)SSED * 256, (long)256 * 32, 32, (long)SSED * 32, 32);
    k_dw3<<<(3 * SSED + 255) / 256, 256>>>(pZ2, dW3, db3, out);

    // ----- decoder: pred_feat -----
    k_hgemm<1, 1><<<g1, 256>>>(pHsh, pWf1h, fb1, pY1h, SSED, 256, 64,
                               0, (long)64 * 256, 256, (long)SSED * 256, 256);
    dim3 g3(16, SSED / 128, 3);   // N=2048
    k_hgemm<1, 1><<<g3, 256>>>(pY1h, pWf2h, fb2, pY2h, SSED, 2048, 256,
                               (long)SSED * 256, (long)256 * 2048, 2048,
                               (long)SSED * 2048, 2048);
    dim3 g4(3, SSED / 128, 3);    // N=320
    k_hgemm<3, 0><<<g4, 256>>>(pY2h, pWf3h, fb3, out + 1, SSED, 320, 2048,
                               (long)SSED * 2048, (long)2048 * 320, 320,
                               (long)SSED * 321, 321);
}

// round 8
// speedup vs baseline: 2.2022x; 1.0435x over previous
#include <cuda_runtime.h>
#include <cuda_fp16.h>
#include <math.h>

#define NN 50000
#define NNP 50048
#define EE 800000
#define SSED 8192
#define HD 64

// ---------------- scratch (device globals) ----------------------------------
__device__ int    g_off[3][NN + 1];
__device__ int    g_cur[3 * NN];
__device__ int    g_esrc[3][EE];
__device__ __half g_xh[NN * HD];
__device__ float  g_S[NNP * 192];       // [node][r*64+q]; pad rows stay 0
__device__ float  g_h1[NNP * HD];
__device__ float  g_h2[SSED * HD];
__device__ __half g_hsh[SSED * HD];
__device__ float  g_zd2[3 * SSED * 32];
__device__ __half g_y1h[3 * SSED * 256];   // z1h then y1h (sequential reuse)
__device__ __half g_y2h[3 * SSED * 2048];
__device__ __half g_wd1h[3 * 64 * 256];
__device__ __half g_wd2h[3 * 256 * 32];
__device__ __half g_wf1h[3 * 64 * 256];
__device__ __half g_wf2h[3 * 256 * 2048];
__device__ __half g_wf3h[3 * 2048 * 320];

// ---------------- fused conversion + counter zeroing -------------------------
#define CVT_XN (NN * HD)          // 3,200,000
#define CVT_D1 (3 * 64 * 256)     // 49,152
#define CVT_D2 (3 * 256 * 32)     // 24,576
#define CVT_F1 (3 * 64 * 256)
#define CVT_F2 (3 * 256 * 2048)   // 1,572,864
#define CVT_F3 (3 * 2048 * 320)   // 1,966,080
#define CVT_TOT (CVT_XN + CVT_D1 + CVT_D2 + CVT_F1 + CVT_F2 + CVT_F3 + 3 * NN)

__global__ void k_convert(const float* __restrict__ x, const float* __restrict__ dW1,
                          const float* __restrict__ dW2, const float* __restrict__ fW1,
                          const float* __restrict__ fW2, const float* __restrict__ fW3) {
    long i = (long)blockIdx.x * blockDim.x + threadIdx.x;
    if (i >= CVT_TOT) return;
    long j = i;
    if (j < CVT_XN) { g_xh[j] = __float2half_rn(x[j]); return; }
    j -= CVT_XN;
    if (j < CVT_D1) { g_wd1h[j] = __float2half_rn(dW1[j]); return; }
    j -= CVT_D1;
    if (j < CVT_D2) { g_wd2h[j] = __float2half_rn(dW2[j]); return; }
    j -= CVT_D2;
    if (j < CVT_F1) { g_wf1h[j] = __float2half_rn(fW1[j]); return; }
    j -= CVT_F1;
    if (j < CVT_F2) { g_wf2h[j] = __float2half_rn(fW2[j]); return; }
    j -= CVT_F2;
    if (j < CVT_F3) { g_wf3h[j] = __float2half_rn(fW3[j]); return; }
    j -= CVT_F3;
    g_cur[j] = 0;
}

// ---------------- CSR construction ------------------------------------------
__global__ void k_cnt(const int* __restrict__ d0, const int* __restrict__ d1,
                      const int* __restrict__ d2) {
    const int r = blockIdx.y;
    const int* d = (r == 0) ? d0 : ((r == 1) ? d1 : d2);
    int e = blockIdx.x * blockDim.x + threadIdx.x;
    if (e < EE) atomicAdd(&g_cur[r * NN + d[e]], 1);
}

__global__ void k_scan() {
    const int r = blockIdx.x;
    const int tid = threadIdx.x;
    __shared__ int sm[1024];
    const int CH = 49;
    int t0 = tid * CH;
    int t1 = t0 + CH; if (t1 > NN) t1 = NN;
    int sum = 0;
    for (int i = t0; i < t1; i++) sum += g_cur[r * NN + i];
    sm[tid] = sum;
    __syncthreads();
#pragma unroll
    for (int o = 1; o < 1024; o <<= 1) {
        int v = (tid >= o) ? sm[tid - o] : 0;
        __syncthreads();
        sm[tid] += v;
        __syncthreads();
    }
    int run = sm[tid] - sum;
    for (int i = t0; i < t1; i++) {
        int c = g_cur[r * NN + i];
        g_off[r][i] = run;
        run += c;
        g_cur[r * NN + i] = 0;
    }
    if (tid == 1023) g_off[r][NN] = run;
}

__global__ void k_fill(const int* __restrict__ s0, const int* __restrict__ d0,
                       const int* __restrict__ s1, const int* __restrict__ d1,
                       const int* __restrict__ s2, const int* __restrict__ d2) {
    const int r = blockIdx.y;
    const int* s = (r == 0) ? s0 : ((r == 1) ? s1 : s2);
    const int* d = (r == 0) ? d0 : ((r == 1) ? d1 : d2);
    int e = blockIdx.x * blockDim.x + threadIdx.x;
    if (e < EE) {
        int dv = d[e];
        int pos = g_off[r][dv] + atomicAdd(&g_cur[r * NN + dv], 1);
        g_esrc[r][pos] = s[e];
    }
}

// ---------------- gathers ----------------------------------------------------
__device__ __forceinline__ void addh8(float* a, uint4 v) {
    const __half2* hv = (const __half2*)&v;
#pragma unroll
    for (int k = 0; k < 4; k++) {
        float2 f = __half22float2(hv[k]);
        a[2 * k] += f.x;
        a[2 * k + 1] += f.y;
    }
}

// layer-1 gather from fp16 x: 8 thr per node, each 8 cols; MLP=4
__global__ void k_gather_h(const __half* __restrict__ h) {
    const int r = blockIdx.y;
    int node = blockIdx.x * 32 + (threadIdx.x >> 3);
    if (node >= NN) return;
    const int q = (threadIdx.x & 7) << 3;
    const int b = g_off[r][node], e2 = g_off[r][node + 1];
    const int* es = g_esrc[r];
    float a0[8] = {0,0,0,0,0,0,0,0}, a1[8] = {0,0,0,0,0,0,0,0};
    float a2[8] = {0,0,0,0,0,0,0,0}, a3[8] = {0,0,0,0,0,0,0,0};
    int i = b;
    for (; i + 4 <= e2; i += 4) {
        int s0 = __ldg(es + i), s1 = __ldg(es + i + 1);
        int s2 = __ldg(es + i + 2), s3 = __ldg(es + i + 3);
        uint4 v0 = *(const uint4*)(h + (long)s0 * HD + q);
        uint4 v1 = *(const uint4*)(h + (long)s1 * HD + q);
        uint4 v2 = *(const uint4*)(h + (long)s2 * HD + q);
        uint4 v3 = *(const uint4*)(h + (long)s3 * HD + q);
        addh8(a0, v0); addh8(a1, v1); addh8(a2, v2); addh8(a3, v3);
    }
    for (; i < e2; i++) {
        uint4 v = *(const uint4*)(h + (long)__ldg(es + i) * HD + q);
        addh8(a0, v);
    }
    float inv = (e2 > b) ? 1.f / (float)(e2 - b) : 1.f;
#pragma unroll
    for (int k = 0; k < 8; k++) a0[k] = (a0[k] + a1[k] + a2[k] + a3[k]) * inv;
    float* dst = g_S + (long)node * 192 + r * HD + q;
    *(float4*)dst = make_float4(a0[0], a0[1], a0[2], a0[3]);
    *(float4*)(dst + 4) = make_float4(a0[4], a0[5], a0[6], a0[7]);
}

// layer-2 gather from fp32 h1: 16 thr per node, MLP=4
__global__ void k_gather(const float* __restrict__ h, int nLimit) {
    const int r = blockIdx.y;
    int node = blockIdx.x * 16 + (threadIdx.x >> 4);
    if (node >= nLimit) return;
    const int q = (threadIdx.x & 15) << 2;
    const int b = g_off[r][node], e2 = g_off[r][node + 1];
    const int* es = g_esrc[r];
    float4 a0 = make_float4(0.f, 0.f, 0.f, 0.f);
    float4 a1 = a0, a2 = a0, a3 = a0;
    int i = b;
    for (; i + 4 <= e2; i += 4) {
        int s0 = __ldg(es + i), s1 = __ldg(es + i + 1);
        int s2 = __ldg(es + i + 2), s3 = __ldg(es + i + 3);
        float4 v0 = *(const float4*)(h + (long)s0 * HD + q);
        float4 v1 = *(const float4*)(h + (long)s1 * HD + q);
        float4 v2 = *(const float4*)(h + (long)s2 * HD + q);
        float4 v3 = *(const float4*)(h + (long)s3 * HD + q);
        a0.x += v0.x; a0.y += v0.y; a0.z += v0.z; a0.w += v0.w;
        a1.x += v1.x; a1.y += v1.y; a1.z += v1.z; a1.w += v1.w;
        a2.x += v2.x; a2.y += v2.y; a2.z += v2.z; a2.w += v2.w;
        a3.x += v3.x; a3.y += v3.y; a3.z += v3.z; a3.w += v3.w;
    }
    for (; i < e2; i++) {
        float4 v = *(const float4*)(h + (long)__ldg(es + i) * HD + q);
        a0.x += v.x; a0.y += v.y; a0.z += v.z; a0.w += v.w;
    }
    a0.x += a1.x + a2.x + a3.x;
    a0.y += a1.y + a2.y + a3.y;
    a0.z += a1.z + a2.z + a3.z;
    a0.w += a1.w + a2.w + a3.w;
    float inv = (e2 > b) ? 1.f / (float)(e2 - b) : 1.f;
    a0.x *= inv; a0.y *= inv; a0.z *= inv; a0.w *= inv;
    *(float4*)(g_S + (long)node * 192 + r * HD + q) = a0;
}

// g_hsh = fp16(leaky_relu(g_h2 @ Wlin + blin) + noise)
__global__ void k_final(const float* __restrict__ W, const float* __restrict__ bias,
                        const float* __restrict__ noise) {
    __shared__ float sW[HD * HD];
    __shared__ float sS[4 * HD];
    for (int i = threadIdx.x; i < HD * HD; i += blockDim.x) sW[i] = W[i];
    __syncthreads();
    const int j = threadIdx.x & 63;
    const int ln = threadIdx.x >> 6;
    for (int n0 = blockIdx.x * 4; n0 < SSED; n0 += gridDim.x * 4) {
        int n = n0 + ln;
        sS[ln * HD + j] = g_h2[(long)n * HD + j];
        __syncthreads();
        float acc = bias[j];
#pragma unroll
        for (int k = 0; k < HD; k++)
            acc = fmaf(sS[ln * HD + k], sW[k * HD + j], acc);
        float v = (acc > 0.f) ? acc : 0.01f * acc;
        g_hsh[(long)n * HD + j] = __float2half_rn(v + noise[(long)n * HD + j]);
        __syncthreads();
    }
}

// ---------------- common asm helpers ----------------------------------------
__device__ __forceinline__ void cp16(void* smem, const void* gmem, bool valid) {
    unsigned s = (unsigned)__cvta_generic_to_shared(smem);
    int sz = valid ? 16 : 0;
    asm volatile("cp.async.cg.shared.global [%0], [%1], 16, %2;"
                 :: "r"(s), "l"(gmem), "r"(sz) : "memory");
}
__device__ __forceinline__ unsigned tf32(float f) {
    unsigned u;
    asm("cvt.rna.tf32.f32 %0, %1;" : "=r"(u) : "f"(f));
    return u;
}
__device__ __forceinline__ void mma8(float* c, const unsigned* a, const unsigned* b) {
    asm volatile("mma.sync.aligned.m16n8k8.row.col.f32.tf32.tf32.f32 "
                 "{%0,%1,%2,%3}, {%4,%5,%6,%7}, {%8,%9}, {%0,%1,%2,%3};"
                 : "+f"(c[0]), "+f"(c[1]), "+f"(c[2]), "+f"(c[3])
                 : "r"(a[0]), "r"(a[1]), "r"(a[2]), "r"(a[3]), "r"(b[0]), "r"(b[1]));
}
__device__ __forceinline__ void mma16h(float* c, const unsigned* a, const unsigned* b) {
    asm volatile("mma.sync.aligned.m16n8k16.row.col.f32.f16.f16.f32 "
                 "{%0,%1,%2,%3}, {%4,%5,%6,%7}, {%8,%9}, {%0,%1,%2,%3};"
                 : "+f"(c[0]), "+f"(c[1]), "+f"(c[2]), "+f"(c[3])
                 : "r"(a[0]), "r"(a[1]), "r"(a[2]), "r"(a[3]), "r"(b[0]), "r"(b[1]));
}
__device__ __forceinline__ void ldsm_x4(unsigned& r0, unsigned& r1, unsigned& r2,
                                        unsigned& r3, const void* p) {
    unsigned a = (unsigned)__cvta_generic_to_shared(p);
    asm volatile("ldmatrix.sync.aligned.m8n8.x4.shared.b16 {%0,%1,%2,%3}, [%4];"
                 : "=r"(r0), "=r"(r1), "=r"(r2), "=r"(r3) : "r"(a));
}
__device__ __forceinline__ void ldsm_x2t(unsigned& r0, unsigned& r1, const void* p) {
    unsigned a = (unsigned)__cvta_generic_to_shared(p);
    asm volatile("ldmatrix.sync.aligned.m8n8.x2.trans.shared.b16 {%0,%1}, [%2];"
                 : "=r"(r0), "=r"(r1) : "r"(a));
}

// ---------------- fp16 tensor-core GEMM (128x128 CTA, 64x32 warp, BK=32) ----
template <int ACT, int HOUT>
__global__ void __launch_bounds__(256, 2)
k_hgemm(const __half* __restrict__ Aall, const __half* __restrict__ Ball,
        const float* __restrict__ biasAll, void* __restrict__ Call,
        int M, int N, int K, long sA, long sB, long sBias, long sC, int ldc) {
    const int r = blockIdx.z;
    const __half* A = Aall + (long)r * sA;
    const __half* B = Ball + (long)r * sB;
    const float* bias = biasAll + (long)r * sBias;

    __shared__ __half As[2][128][40];
    __shared__ __half Bs[2][32][136];

    const int t = threadIdx.x;
    const int lane = t & 31;
    const int warp = t >> 5;
    const int wm = (warp >> 2) * 64;
    const int wn = (warp & 3) * 32;
    const long bm = (long)blockIdx.y * 128;
    const int bn = blockIdx.x * 128;

    const int aRow = t >> 1;
    const int aCol = (t & 1) << 4;
    const int bRow = t >> 3;
    const int bCol = (t & 7) << 4;
    const bool bv0 = (bn + bCol) < N;
    const bool bv1 = (bn + bCol + 8) < N;
    const int bc0 = bv0 ? bn + bCol : 0;
    const int bc1 = bv1 ? bn + bCol + 8 : 0;

    const int gid = lane >> 2;
    const int tig = lane & 3;

    float acc[4][4][4];
#pragma unroll
    for (int i = 0; i < 4; i++)
#pragma unroll
        for (int j = 0; j < 4; j++)
#pragma unroll
            for (int c = 0; c < 4; c++) acc[i][j][c] = 0.f;

    const int KT = K / 32;

    {
        cp16(&As[0][aRow][aCol], A + (bm + aRow) * (long)K + aCol, true);
        cp16(&As[0][aRow][aCol + 8], A + (bm + aRow) * (long)K + aCol + 8, true);
        cp16(&Bs[0][bRow][bCol], B + (long)bRow * N + bc0, bv0);
        cp16(&Bs[0][bRow][bCol + 8], B + (long)bRow * N + bc1, bv1);
        asm volatile("cp.async.commit_group;" ::: "memory");
        asm volatile("cp.async.wait_group 0;" ::: "memory");
        __syncthreads();
    }

    const int aFragRow = lane & 15;
    const int aFragCol = (lane >> 4) << 3;

    for (int kt = 0; kt < KT; kt++) {
        const int cb = kt & 1, nb = (kt + 1) & 1;
        if (kt + 1 < KT) {
            long ko = (long)(kt + 1) * 32;
            cp16(&As[nb][aRow][aCol], A + (bm + aRow) * (long)K + ko + aCol, true);
            cp16(&As[nb][aRow][aCol + 8], A + (bm + aRow) * (long)K + ko + aCol + 8, true);
            cp16(&Bs[nb][bRow][bCol], B + (ko + bRow) * (long)N + bc0, bv0);
            cp16(&Bs[nb][bRow][bCol + 8], B + (ko + bRow) * (long)N + bc1, bv1);
            asm volatile("cp.async.commit_group;" ::: "memory");
        }
#pragma unroll
        for (int kk = 0; kk < 2; kk++) {
            const int k0 = kk * 16;
            unsigned a[4][4], b[4][2];
#pragma unroll
            for (int tm = 0; tm < 4; tm++)
                ldsm_x4(a[tm][0], a[tm][1], a[tm][2], a[tm][3],
                        &As[cb][wm + tm * 16 + aFragRow][k0 + aFragCol]);
#pragma unroll
            for (int tn = 0; tn < 4; tn++)
                ldsm_x2t(b[tn][0], b[tn][1],
                         &Bs[cb][k0 + (lane & 15)][wn + tn * 8]);
#pragma unroll
            for (int tm = 0; tm < 4; tm++)
#pragma unroll
                for (int tn = 0; tn < 4; tn++)
                    mma16h(acc[tm][tn], a[tm], b[tn]);
        }
        if (kt + 1 < KT)
            asm volatile("cp.async.wait_group 0;" ::: "memory");
        __syncthreads();
    }

#pragma unroll
    for (int tm = 0; tm < 4; tm++) {
        long row0 = bm + wm + tm * 16 + gid;
#pragma unroll
        for (int tn = 0; tn < 4; tn++) {
            int col = bn + wn + tn * 8 + tig * 2;
            if (col < N) {
                float bs0 = bias[col], bs1 = bias[col + 1];
#pragma unroll
                for (int h = 0; h < 2; h++) {
                    long row = row0 + h * 8;
                    float u0 = acc[tm][tn][h * 2 + 0] + bs0;
                    float u1 = acc[tm][tn][h * 2 + 1] + bs1;
                    if (ACT == 1) { u0 = fmaxf(u0, 0.f); u1 = fmaxf(u1, 0.f); }
                    else if (ACT == 2) { u0 = (u0 > 0.f) ? u0 : 0.01f * u0;
                                         u1 = (u1 > 0.f) ? u1 : 0.01f * u1; }
                    else { u0 = tanhf(u0); u1 = tanhf(u1); }
                    if (HOUT) {
                        __half* C = (__half*)Call + (long)r * sC;
                        *(__half2*)(C + row * ldc + col) = __floats2half2_rn(u0, u1);
                    } else {
                        float* C = (float*)Call + (long)r * sC;
                        C[row * ldc + col] = u0;
                        C[row * ldc + col + 1] = u1;
                    }
                }
            }
        }
    }
}

// ---------------- TF32 tensor-core GEMM (conv combines) ---------------------
template <int ACT>
__global__ void __launch_bounds__(256, 2)
k_tgemm(const float* __restrict__ Aall, const float* __restrict__ Ball,
        const float* __restrict__ biasAll, float* __restrict__ Call,
        int M, int N, int K, long sA, long sB, long sBias, long sC, int ldc) {
    const int r = blockIdx.z;
    const float* A = Aall + (long)r * sA;
    const float* B = Ball + (long)r * sB;
    const float* bias = biasAll + (long)r * sBias;
    float* C = Call + (long)r * sC;

    __shared__ float As[2][128][20];
    __shared__ float Bs[2][16][136];

    const int t = threadIdx.x;
    const int lane = t & 31;
    const int warp = t >> 5;
    const int wm = (warp >> 2) * 64;
    const int wn = (warp & 3) * 32;
    const long bm = (long)blockIdx.y * 128;
    const int bn = blockIdx.x * 128;

    const int aRow = t >> 2;
    const int aCol = (t & 3) << 2;
    const int bRow = t >> 5;
    const int bCol = (t & 31) << 2;
    const bool bValid = (bn + bCol) < N;
    const int bnc = bValid ? bn + bCol : 0;

    const int gid = lane >> 2;
    const int tig = lane & 3;

    float acc[4][4][4];
#pragma unroll
    for (int i = 0; i < 4; i++)
#pragma unroll
        for (int j = 0; j < 4; j++)
#pragma unroll
            for (int c = 0; c < 4; c++) acc[i][j][c] = 0.f;

    const int KT = K / 16;

    {
        cp16(&As[0][aRow][aCol], A + (bm + aRow) * (long)K + aCol, true);
        cp16(&As[0][aRow + 64][aCol], A + (bm + aRow + 64) * (long)K + aCol, true);
        cp16(&Bs[0][bRow][bCol], B + (long)bRow * N + bnc, bValid);
        cp16(&Bs[0][bRow + 8][bCol], B + (long)(bRow + 8) * N + bnc, bValid);
        asm volatile("cp.async.commit_group;" ::: "memory");
        asm volatile("cp.async.wait_group 0;" ::: "memory");
        __syncthreads();
    }

    for (int kt = 0; kt < KT; kt++) {
        const int cb = kt & 1, nb = (kt + 1) & 1;
        if (kt + 1 < KT) {
            long ko = (long)(kt + 1) * 16;
            cp16(&As[nb][aRow][aCol], A + (bm + aRow) * (long)K + ko + aCol, true);
            cp16(&As[nb][aRow + 64][aCol], A + (bm + aRow + 64) * (long)K + ko + aCol, true);
            cp16(&Bs[nb][bRow][bCol], B + (ko + bRow) * (long)N + bnc, bValid);
            cp16(&Bs[nb][bRow + 8][bCol], B + (ko + bRow + 8) * (long)N + bnc, bValid);
            asm volatile("cp.async.commit_group;" ::: "memory");
        }
#pragma unroll
        for (int k8 = 0; k8 < 2; k8++) {
            const int k0 = k8 * 8;
            unsigned a[4][4], b[4][2];
#pragma unroll
            for (int tm = 0; tm < 4; tm++) {
                int m = wm + tm * 16 + gid;
                a[tm][0] = tf32(As[cb][m][k0 + tig]);
                a[tm][1] = tf32(As[cb][m + 8][k0 + tig]);
                a[tm][2] = tf32(As[cb][m][k0 + tig + 4]);
                a[tm][3] = tf32(As[cb][m + 8][k0 + tig + 4]);
            }
#pragma unroll
            for (int tn = 0; tn < 4; tn++) {
                int n = wn + tn * 8 + gid;
                b[tn][0] = tf32(Bs[cb][k0 + tig][n]);
                b[tn][1] = tf32(Bs[cb][k0 + tig + 4][n]);
            }
#pragma unroll
            for (int tm = 0; tm < 4; tm++)
#pragma unroll
                for (int tn = 0; tn < 4; tn++)
                    mma8(acc[tm][tn], a[tm], b[tn]);
        }
        if (kt + 1 < KT)
            asm volatile("cp.async.wait_group 0;" ::: "memory");
        __syncthreads();
    }

#pragma unroll
    for (int tm = 0; tm < 4; tm++) {
        long row0 = bm + wm + tm * 16 + gid;
#pragma unroll
        for (int tn = 0; tn < 4; tn++) {
            int col = bn + wn + tn * 8 + tig * 2;
            if (col < N) {
                float bs0 = bias[col], bs1 = bias[col + 1];
#pragma unroll
                for (int h = 0; h < 2; h++) {
                    long row = row0 + h * 8;
                    float u0 = acc[tm][tn][h * 2 + 0] + bs0;
                    float u1 = acc[tm][tn][h * 2 + 1] + bs1;
                    if (ACT == 1) { u0 = fmaxf(u0, 0.f); u1 = fmaxf(u1, 0.f); }
                    else if (ACT == 2) { u0 = (u0 > 0.f) ? u0 : 0.01f * u0;
                                         u1 = (u1 > 0.f) ? u1 : 0.01f * u1; }
                    else { u0 = tanhf(u0); u1 = tanhf(u1); }
                    C[row * ldc + col] = u0;
                    C[row * ldc + col + 1] = u1;
                }
            }
        }
    }
}

// pred_missing head
__global__ void k_dw3(const float* __restrict__ z, const float* __restrict__ W,
                      const float* __restrict__ b, float* __restrict__ out) {
    int i = blockIdx.x * blockDim.x + threadIdx.x;
    if (i >= 3 * SSED) return;
    int r = i / SSED;
    int s = i % SSED;
    const float* zz = z + ((long)r * SSED + s) * 32;
    const float* w = W + r * 32;
    float acc = b[r];
#pragma unroll
    for (int k = 0; k < 32; k++) acc = fmaf(zz[k], w[k], acc);
    out[((long)r * SSED + s) * 321] = fmaxf(acc, 0.f);
}

// ---------------- host launch ----------------------------------------------
extern "C" void kernel_launch(void* const* d_in, const int* in_sizes, int n_in,
                              void* d_out, int out_size) {
    static const int MAP_DICT[27] = {0,1,2,3,4,5,6,7,8,9,10,11,12,13,14,15,16,17,18,19,20,21,22,23,24,25,26};
    static const int MAP_SIG[27]  = {0,1,20,21,22,23,24,25,26,2,3,4,5,6,7,8,9,10,11,12,13,14,15,16,17,18,19};
    static const int MAP_ALPHA[27]= {26,21,22,23,12,24,13,25,14,0,3,1,4,2,5,6,9,7,10,8,11,15,18,16,19,17,20};
    const int* MAP = MAP_DICT;
    if (n_in >= 3) {
        if (in_sizes[2] == 12288) MAP = MAP_SIG;
        else if (in_sizes[2] == 4096) MAP = MAP_ALPHA;
    }

    const float* x     = (const float*)d_in[MAP[0]];
    const float* noise = (const float*)d_in[MAP[1]];
    const int* src[3]  = {(const int*)d_in[MAP[3]], (const int*)d_in[MAP[5]], (const int*)d_in[MAP[7]]};
    const int* dst[3]  = {(const int*)d_in[MAP[4]], (const int*)d_in[MAP[6]], (const int*)d_in[MAP[8]]};
    const float* Wc1   = (const float*)d_in[MAP[9]];
    const float* bc1   = (const float*)d_in[MAP[10]];
    const float* Wc2   = (const float*)d_in[MAP[11]];
    const float* bc2   = (const float*)d_in[MAP[12]];
    const float* Wlin  = (const float*)d_in[MAP[13]];
    const float* blin  = (const float*)d_in[MAP[14]];
    const float* dW1   = (const float*)d_in[MAP[15]];
    const float* db1   = (const float*)d_in[MAP[16]];
    const float* dW2   = (const float*)d_in[MAP[17]];
    const float* db2   = (const float*)d_in[MAP[18]];
    const float* dW3   = (const float*)d_in[MAP[19]];
    const float* db3   = (const float*)d_in[MAP[20]];
    const float* fW1   = (const float*)d_in[MAP[21]];
    const float* fb1   = (const float*)d_in[MAP[22]];
    const float* fW2   = (const float*)d_in[MAP[23]];
    const float* fb2   = (const float*)d_in[MAP[24]];
    const float* fW3   = (const float*)d_in[MAP[25]];
    const float* fb3   = (const float*)d_in[MAP[26]];
    float* out = (float*)d_out;

    float *pS, *pH1, *pH2, *pZ2;
    __half *pXh, *pHsh, *pY1h, *pY2h, *pWd1h, *pWd2h, *pWf1h, *pWf2h, *pWf3h;
    cudaGetSymbolAddress((void**)&pS,    g_S);
    cudaGetSymbolAddress((void**)&pH1,   g_h1);
    cudaGetSymbolAddress((void**)&pH2,   g_h2);
    cudaGetSymbolAddress((void**)&pZ2,   g_zd2);
    cudaGetSymbolAddress((void**)&pXh,   g_xh);
    cudaGetSymbolAddress((void**)&pHsh,  g_hsh);
    cudaGetSymbolAddress((void**)&pY1h,  g_y1h);
    cudaGetSymbolAddress((void**)&pY2h,  g_y2h);
    cudaGetSymbolAddress((void**)&pWd1h, g_wd1h);
    cudaGetSymbolAddress((void**)&pWd2h, g_wd2h);
    cudaGetSymbolAddress((void**)&pWf1h, g_wf1h);
    cudaGetSymbolAddress((void**)&pWf2h, g_wf2h);
    cudaGetSymbolAddress((void**)&pWf3h, g_wf3h);

    // ----- fused conversions + counter zero -----
    k_convert<<<(int)((CVT_TOT + 255) / 256), 256>>>(x, dW1, dW2, fW1, fW2, fW3);

    // ----- CSR build -----
    {
        dim3 g((EE + 255) / 256, 3);
        k_cnt<<<g, 256>>>(dst[0], dst[1], dst[2]);
        k_scan<<<3, 1024>>>();
        k_fill<<<g, 256>>>(src[0], dst[0], src[1], dst[1], src[2], dst[2]);
    }

    // ----- conv layer 1 (fp16 gather) -----
    {
        dim3 g((NN + 31) / 32, 3);
        k_gather_h<<<g, 256>>>(pXh);
    }
    k_tgemm<1><<<dim3(1, NNP / 128, 1), 256>>>(pS, Wc1, bc1, pH1,
                                               NNP, 64, 192, 0, 0, 0, 0, 64);

    // ----- conv layer 2 -----
    {
        dim3 g(SSED / 16, 3);
        k_gather<<<g, 256>>>(pH1, SSED);
    }
    k_tgemm<1><<<dim3(1, SSED / 128, 1), 256>>>(pS, Wc2, bc2, pH2,
                                                SSED, 64, 192, 0, 0, 0, 0, 64);

    // ----- final linear (fp16 hs) -----
    k_final<<<2048, 256>>>(Wlin, blin, noise);

    // ----- decoder: pred_missing -----
    dim3 g1(2, SSED / 128, 3);    // N=256
    k_hgemm<2, 1><<<g1, 256>>>(pHsh, pWd1h, db1, pY1h, SSED, 256, 64,
                               0, (long)64 * 256, 256, (long)SSED * 256, 256);
    dim3 g2(1, SSED / 128, 3);    // N=32 (tensor path, masked tile)
    k_hgemm<2, 0><<<g2, 256>>>(pY1h, pWd2h, db2, pZ2, SSED, 32, 256,
                               (long)SSED * 256, (long)256 * 32, 32,
                               (long)SSED * 32, 32);
    k_dw3<<<(3 * SSED + 255) / 256, 256>>>(pZ2, dW3, db3, out);

    // ----- decoder: pred_feat -----
    k_hgemm<1, 1><<<g1, 256>>>(pHsh, pWf1h, fb1, pY1h, SSED, 256, 64,
                               0, (long)64 * 256, 256, (long)SSED * 256, 256);
    dim3 g3(16, SSED / 128, 3);   // N=2048
    k_hgemm<1, 1><<<g3, 256>>>(pY1h, pWf2h, fb2, pY2h, SSED, 2048, 256,
                               (long)SSED * 256, (long)256 * 2048, 2048,
                               (long)SSED * 2048, 2048);
    dim3 g4(3, SSED / 128, 3);    // N=320
    k_hgemm<3, 0><<<g4, 256>>>(pY2h, pWf3h, fb3, out + 1, SSED, 320, 2048,
                               (long)SSED * 2048, (long)2048 * 320, 320,
                               (long)SSED * 321, 321);
}

// round 10
// speedup vs baseline: 2.2210x; 1.0085x over previous
#include <cuda_runtime.h>
#include <cuda_fp16.h>
#include <math.h>

#define NN 50000
#define NNP 50048
#define EE 800000
#define SSED 8192
#define HD 64

// ---------------- scratch (device globals) ----------------------------------
__device__ int    g_off[3][NN + 1];
__device__ int    g_cur[3 * NN];        // zero-initialized; self-restoring per call
__device__ int    g_esrc[3][EE];
__device__ __half g_xh[NN * HD];
__device__ float  g_S[NNP * 192];
__device__ float  g_h1[NNP * HD];
__device__ float  g_h2[SSED * HD];
__device__ __half g_hsh[SSED * HD];
__device__ float  g_zd2[3 * SSED * 32];
__device__ __half g_y1h[3 * SSED * 256];
__device__ __half g_y2h[3 * SSED * 2048];
__device__ __half g_wd1h[3 * 64 * 256];
__device__ __half g_wd2h[3 * 256 * 32];
__device__ __half g_wf1h[3 * 64 * 256];
__device__ __half g_wf2h[3 * 256 * 2048];
__device__ __half g_wf3h[3 * 2048 * 320];

// ---------------- fused conversion + degree count ----------------------------
#define CVT_XN (NN * HD)
#define CVT_D1 (3 * 64 * 256)
#define CVT_D2 (3 * 256 * 32)
#define CVT_F1 (3 * 64 * 256)
#define CVT_F2 (3 * 256 * 2048)
#define CVT_F3 (3 * 2048 * 320)
#define CVT_TOT ((long)CVT_XN + CVT_D1 + CVT_D2 + CVT_F1 + CVT_F2 + CVT_F3 + 3L * EE)

// g_cur must be zero on entry (static init on call 1; k_gather_h re-zeroes each call)
__global__ void k_convert(const float* __restrict__ x, const float* __restrict__ dW1,
                          const float* __restrict__ dW2, const float* __restrict__ fW1,
                          const float* __restrict__ fW2, const float* __restrict__ fW3,
                          const int* __restrict__ d0, const int* __restrict__ d1,
                          const int* __restrict__ d2) {
    long i = (long)blockIdx.x * blockDim.x + threadIdx.x;
    if (i >= CVT_TOT) return;
    long j = i;
    if (j < CVT_XN) { g_xh[j] = __float2half_rn(x[j]); return; }
    j -= CVT_XN;
    if (j < CVT_D1) { g_wd1h[j] = __float2half_rn(dW1[j]); return; }
    j -= CVT_D1;
    if (j < CVT_D2) { g_wd2h[j] = __float2half_rn(dW2[j]); return; }
    j -= CVT_D2;
    if (j < CVT_F1) { g_wf1h[j] = __float2half_rn(fW1[j]); return; }
    j -= CVT_F1;
    if (j < CVT_F2) { g_wf2h[j] = __float2half_rn(fW2[j]); return; }
    j -= CVT_F2;
    if (j < CVT_F3) { g_wf3h[j] = __float2half_rn(fW3[j]); return; }
    j -= CVT_F3;
    // degree counting
    int r = (int)(j / EE);
    int e = (int)(j % EE);
    const int* d = (r == 0) ? d0 : ((r == 1) ? d1 : d2);
    atomicAdd(&g_cur[r * NN + d[e]], 1);
}

// ---------------- CSR scan + fill --------------------------------------------
__global__ void k_scan() {
    const int r = blockIdx.x;
    const int tid = threadIdx.x;
    __shared__ int sm[1024];
    const int CH = 49;
    int t0 = tid * CH;
    int t1 = t0 + CH; if (t1 > NN) t1 = NN;
    int sum = 0;
    for (int i = t0; i < t1; i++) sum += g_cur[r * NN + i];
    sm[tid] = sum;
    __syncthreads();
#pragma unroll
    for (int o = 1; o < 1024; o <<= 1) {
        int v = (tid >= o) ? sm[tid - o] : 0;
        __syncthreads();
        sm[tid] += v;
        __syncthreads();
    }
    int run = sm[tid] - sum;
    for (int i = t0; i < t1; i++) {
        int c = g_cur[r * NN + i];
        g_off[r][i] = run;
        run += c;
        g_cur[r * NN + i] = 0;          // reset for fill cursors
    }
    if (tid == 1023) g_off[r][NN] = run;
}

__global__ void k_fill(const int* __restrict__ s0, const int* __restrict__ d0,
                       const int* __restrict__ s1, const int* __restrict__ d1,
                       const int* __restrict__ s2, const int* __restrict__ d2) {
    const int r = blockIdx.y;
    const int* s = (r == 0) ? s0 : ((r == 1) ? s1 : s2);
    const int* d = (r == 0) ? d0 : ((r == 1) ? d1 : d2);
    int e = blockIdx.x * blockDim.x + threadIdx.x;
    if (e < EE) {
        int dv = d[e];
        int pos = g_off[r][dv] + atomicAdd(&g_cur[r * NN + dv], 1);
        g_esrc[r][pos] = s[e];
    }
}

// ---------------- gathers ----------------------------------------------------
__device__ __forceinline__ void addh8(float* a, uint4 v) {
    const __half2* hv = (const __half2*)&v;
#pragma unroll
    for (int k = 0; k < 4; k++) {
        float2 f = __half22float2(hv[k]);
        a[2 * k] += f.x;
        a[2 * k + 1] += f.y;
    }
}

// layer-1 gather fp16: 16 thr/node = two 8-lane groups splitting the edge list.
// Also re-zeroes g_cur (post-fill) so next call's k_convert counts from zero.
__global__ void k_gather_h(const __half* __restrict__ h) {
    const int r = blockIdx.y;
    const int t = threadIdx.x;
    int node = blockIdx.x * 16 + (t >> 4);
    if (node >= NN) return;
    if ((t & 15) == 0) g_cur[r * NN + node] = 0;
    const int sub = (t >> 3) & 1;
    const int q = (t & 7) << 3;
    const int b = g_off[r][node], e2 = g_off[r][node + 1];
    const int cnt = e2 - b;
    const int half = (cnt + 1) >> 1;
    const int gb = b + sub * half;
    const int ge = sub ? e2 : b + half;
    const int* es = g_esrc[r];
    float a0[8] = {0,0,0,0,0,0,0,0}, a1[8] = {0,0,0,0,0,0,0,0};
    float a2[8] = {0,0,0,0,0,0,0,0}, a3[8] = {0,0,0,0,0,0,0,0};
    int i = gb;
    for (; i + 4 <= ge; i += 4) {
        int s0 = __ldg(es + i), s1 = __ldg(es + i + 1);
        int s2 = __ldg(es + i + 2), s3 = __ldg(es + i + 3);
        uint4 v0 = *(const uint4*)(h + (long)s0 * HD + q);
        uint4 v1 = *(const uint4*)(h + (long)s1 * HD + q);
        uint4 v2 = *(const uint4*)(h + (long)s2 * HD + q);
        uint4 v3 = *(const uint4*)(h + (long)s3 * HD + q);
        addh8(a0, v0); addh8(a1, v1); addh8(a2, v2); addh8(a3, v3);
    }
    for (; i < ge; i++) {
        uint4 v = *(const uint4*)(h + (long)__ldg(es + i) * HD + q);
        addh8(a0, v);
    }
    float inv = (cnt > 0) ? 1.f / (float)cnt : 1.f;
#pragma unroll
    for (int k = 0; k < 8; k++) {
        float v = a0[k] + a1[k] + a2[k] + a3[k];
        v += __shfl_xor_sync(0xffffffffu, v, 8);
        a0[k] = v * inv;
    }
    if (sub == 0) {
        float* dst = g_S + (long)node * 192 + r * HD + q;
        *(float4*)dst = make_float4(a0[0], a0[1], a0[2], a0[3]);
        *(float4*)(dst + 4) = make_float4(a0[4], a0[5], a0[6], a0[7]);
    }
}

// layer-2 gather from fp32 h1: 16 thr per node, MLP=4
__global__ void k_gather(const float* __restrict__ h, int nLimit) {
    const int r = blockIdx.y;
    int node = blockIdx.x * 16 + (threadIdx.x >> 4);
    if (node >= nLimit) return;
    const int q = (threadIdx.x & 15) << 2;
    const int b = g_off[r][node], e2 = g_off[r][node + 1];
    const int* es = g_esrc[r];
    float4 a0 = make_float4(0.f, 0.f, 0.f, 0.f);
    float4 a1 = a0, a2 = a0, a3 = a0;
    int i = b;
    for (; i + 4 <= e2; i += 4) {
        int s0 = __ldg(es + i), s1 = __ldg(es + i + 1);
        int s2 = __ldg(es + i + 2), s3 = __ldg(es + i + 3);
        float4 v0 = *(const float4*)(h + (long)s0 * HD + q);
        float4 v1 = *(const float4*)(h + (long)s1 * HD + q);
        float4 v2 = *(const float4*)(h + (long)s2 * HD + q);
        float4 v3 = *(const float4*)(h + (long)s3 * HD + q);
        a0.x += v0.x; a0.y += v0.y; a0.z += v0.z; a0.w += v0.w;
        a1.x += v1.x; a1.y += v1.y; a1.z += v1.z; a1.w += v1.w;
        a2.x += v2.x; a2.y += v2.y; a2.z += v2.z; a2.w += v2.w;
        a3.x += v3.x; a3.y += v3.y; a3.z += v3.z; a3.w += v3.w;
    }
    for (; i < e2; i++) {
        float4 v = *(const float4*)(h + (long)__ldg(es + i) * HD + q);
        a0.x += v.x; a0.y += v.y; a0.z += v.z; a0.w += v.w;
    }
    a0.x += a1.x + a2.x + a3.x;
    a0.y += a1.y + a2.y + a3.y;
    a0.z += a1.z + a2.z + a3.z;
    a0.w += a1.w + a2.w + a3.w;
    float inv = (e2 > b) ? 1.f / (float)(e2 - b) : 1.f;
    a0.x *= inv; a0.y *= inv; a0.z *= inv; a0.w *= inv;
    *(float4*)(g_S + (long)node * 192 + r * HD + q) = a0;
}

__global__ void k_final(const float* __restrict__ W, const float* __restrict__ bias,
                        const float* __restrict__ noise) {
    __shared__ float sW[HD * HD];
    __shared__ float sS[4 * HD];
    for (int i = threadIdx.x; i < HD * HD; i += blockDim.x) sW[i] = W[i];
    __syncthreads();
    const int j = threadIdx.x & 63;
    const int ln = threadIdx.x >> 6;
    for (int n0 = blockIdx.x * 4; n0 < SSED; n0 += gridDim.x * 4) {
        int n = n0 + ln;
        sS[ln * HD + j] = g_h2[(long)n * HD + j];
        __syncthreads();
        float acc = bias[j];
#pragma unroll
        for (int k = 0; k < HD; k++)
            acc = fmaf(sS[ln * HD + k], sW[k * HD + j], acc);
        float v = (acc > 0.f) ? acc : 0.01f * acc;
        g_hsh[(long)n * HD + j] = __float2half_rn(v + noise[(long)n * HD + j]);
        __syncthreads();
    }
}

// ---------------- common asm helpers ----------------------------------------
__device__ __forceinline__ void cp16(void* smem, const void* gmem, bool valid) {
    unsigned s = (unsigned)__cvta_generic_to_shared(smem);
    int sz = valid ? 16 : 0;
    asm volatile("cp.async.cg.shared.global [%0], [%1], 16, %2;"
                 :: "r"(s), "l"(gmem), "r"(sz) : "memory");
}
__device__ __forceinline__ unsigned tf32(float f) {
    unsigned u;
    asm("cvt.rna.tf32.f32 %0, %1;" : "=r"(u) : "f"(f));
    return u;
}
__device__ __forceinline__ void mma8(float* c, const unsigned* a, const unsigned* b) {
    asm volatile("mma.sync.aligned.m16n8k8.row.col.f32.tf32.tf32.f32 "
                 "{%0,%1,%2,%3}, {%4,%5,%6,%7}, {%8,%9}, {%0,%1,%2,%3};"
                 : "+f"(c[0]), "+f"(c[1]), "+f"(c[2]), "+f"(c[3])
                 : "r"(a[0]), "r"(a[1]), "r"(a[2]), "r"(a[3]), "r"(b[0]), "r"(b[1]));
}
__device__ __forceinline__ void mma16h(float* c, const unsigned* a, const unsigned* b) {
    asm volatile("mma.sync.aligned.m16n8k16.row.col.f32.f16.f16.f32 "
                 "{%0,%1,%2,%3}, {%4,%5,%6,%7}, {%8,%9}, {%0,%1,%2,%3};"
                 : "+f"(c[0]), "+f"(c[1]), "+f"(c[2]), "+f"(c[3])
                 : "r"(a[0]), "r"(a[1]), "r"(a[2]), "r"(a[3]), "r"(b[0]), "r"(b[1]));
}
__device__ __forceinline__ void ldsm_x4(unsigned& r0, unsigned& r1, unsigned& r2,
                                        unsigned& r3, const void* p) {
    unsigned a = (unsigned)__cvta_generic_to_shared(p);
    asm volatile("ldmatrix.sync.aligned.m8n8.x4.shared.b16 {%0,%1,%2,%3}, [%4];"
                 : "=r"(r0), "=r"(r1), "=r"(r2), "=r"(r3) : "r"(a));
}
__device__ __forceinline__ void ldsm_x4t(unsigned& r0, unsigned& r1, unsigned& r2,
                                         unsigned& r3, const void* p) {
    unsigned a = (unsigned)__cvta_generic_to_shared(p);
    asm volatile("ldmatrix.sync.aligned.m8n8.x4.trans.shared.b16 {%0,%1,%2,%3}, [%4];"
                 : "=r"(r0), "=r"(r1), "=r"(r2), "=r"(r3) : "r"(a));
}

// ---------------- fp16 tensor-core GEMM (128x128 CTA, 64x32 warp, BK=32) ----
template <int ACT, int HOUT>
__global__ void __launch_bounds__(256, 2)
k_hgemm(const __half* __restrict__ Aall, const __half* __restrict__ Ball,
        const float* __restrict__ biasAll, void* __restrict__ Call,
        int M, int N, int K, long sA, long sB, long sBias, long sC, int ldc) {
    const int r = blockIdx.z;
    const __half* A = Aall + (long)r * sA;
    const __half* B = Ball + (long)r * sB;
    const float* bias = biasAll + (long)r * sBias;

    __shared__ __half As[2][128][40];
    __shared__ __half Bs[2][32][136];

    const int t = threadIdx.x;
    const int lane = t & 31;
    const int warp = t >> 5;
    const int wm = (warp >> 2) * 64;
    const int wn = (warp & 3) * 32;
    const long bm = (long)blockIdx.y * 128;
    const int bn = blockIdx.x * 128;

    const int aRow = t >> 1;
    const int aCol = (t & 1) << 4;
    const int bRow = t >> 3;
    const int bCol = (t & 7) << 4;
    const bool bv0 = (bn + bCol) < N;
    const bool bv1 = (bn + bCol + 8) < N;
    const int bc0 = bv0 ? bn + bCol : 0;
    const int bc1 = bv1 ? bn + bCol + 8 : 0;

    const int gid = lane >> 2;
    const int tig = lane & 3;

    float acc[4][4][4];
#pragma unroll
    for (int i = 0; i < 4; i++)
#pragma unroll
        for (int j = 0; j < 4; j++)
#pragma unroll
            for (int c = 0; c < 4; c++) acc[i][j][c] = 0.f;

    const int KT = K / 32;

    {
        cp16(&As[0][aRow][aCol], A + (bm + aRow) * (long)K + aCol, true);
        cp16(&As[0][aRow][aCol + 8], A + (bm + aRow) * (long)K + aCol + 8, true);
        cp16(&Bs[0][bRow][bCol], B + (long)bRow * N + bc0, bv0);
        cp16(&Bs[0][bRow][bCol + 8], B + (long)bRow * N + bc1, bv1);
        asm volatile("cp.async.commit_group;" ::: "memory");
        asm volatile("cp.async.wait_group 0;" ::: "memory");
        __syncthreads();
    }

    const int aFragRow = lane & 15;
    const int aFragCol = (lane >> 4) << 3;
    const int bFragRow = lane & 15;
    const int bFragCol = (lane >> 4) << 3;

    for (int kt = 0; kt < KT; kt++) {
        const int cb = kt & 1, nb = (kt + 1) & 1;
        if (kt + 1 < KT) {
            long ko = (long)(kt + 1) * 32;
            cp16(&As[nb][aRow][aCol], A + (bm + aRow) * (long)K + ko + aCol, true);
            cp16(&As[nb][aRow][aCol + 8], A + (bm + aRow) * (long)K + ko + aCol + 8, true);
            cp16(&Bs[nb][bRow][bCol], B + (ko + bRow) * (long)N + bc0, bv0);
            cp16(&Bs[nb][bRow][bCol + 8], B + (ko + bRow) * (long)N + bc1, bv1);
            asm volatile("cp.async.commit_group;" ::: "memory");
        }
#pragma unroll
        for (int kk = 0; kk < 2; kk++) {
            const int k0 = kk * 16;
            unsigned a[4][4], b[4][2];
#pragma unroll
            for (int tm = 0; tm < 4; tm++)
                ldsm_x4(a[tm][0], a[tm][1], a[tm][2], a[tm][3],
                        &As[cb][wm + tm * 16 + aFragRow][k0 + aFragCol]);
#pragma unroll
            for (int tn2 = 0; tn2 < 2; tn2++)
                ldsm_x4t(b[tn2 * 2][0], b[tn2 * 2][1], b[tn2 * 2 + 1][0], b[tn2 * 2 + 1][1],
                         &Bs[cb][k0 + bFragRow][wn + tn2 * 16 + bFragCol]);
#pragma unroll
            for (int tm = 0; tm < 4; tm++)
#pragma unroll
                for (int tn = 0; tn < 4; tn++)
                    mma16h(acc[tm][tn], a[tm], b[tn]);
        }
        if (kt + 1 < KT)
            asm volatile("cp.async.wait_group 0;" ::: "memory");
        __syncthreads();
    }

#pragma unroll
    for (int tm = 0; tm < 4; tm++) {
        long row0 = bm + wm + tm * 16 + gid;
#pragma unroll
        for (int tn = 0; tn < 4; tn++) {
            int col = bn + wn + tn * 8 + tig * 2;
            if (col < N) {
                float bs0 = bias[col], bs1 = bias[col + 1];
#pragma unroll
                for (int h = 0; h < 2; h++) {
                    long row = row0 + h * 8;
                    float u0 = acc[tm][tn][h * 2 + 0] + bs0;
                    float u1 = acc[tm][tn][h * 2 + 1] + bs1;
                    if (ACT == 1) { u0 = fmaxf(u0, 0.f); u1 = fmaxf(u1, 0.f); }
                    else if (ACT == 2) { u0 = (u0 > 0.f) ? u0 : 0.01f * u0;
                                         u1 = (u1 > 0.f) ? u1 : 0.01f * u1; }
                    else { u0 = tanhf(u0); u1 = tanhf(u1); }
                    if (HOUT) {
                        __half* Cp = (__half*)Call + (long)r * sC;
                        *(__half2*)(Cp + row * ldc + col) = __floats2half2_rn(u0, u1);
                    } else {
                        float* Cp = (float*)Call + (long)r * sC;
                        Cp[row * ldc + col] = u0;
                        Cp[row * ldc + col + 1] = u1;
                    }
                }
            }
        }
    }
}

// ---------------- TF32 tensor GEMM (conv combines) --------------------------
template <int ACT>
__global__ void __launch_bounds__(256, 2)
k_tgemm(const float* __restrict__ Aall, const float* __restrict__ Ball,
        const float* __restrict__ biasAll, float* __restrict__ Call,
        int M, int N, int K, long sA, long sB, long sBias, long sC, int ldc) {
    const int r = blockIdx.z;
    const float* A = Aall + (long)r * sA;
    const float* B = Ball + (long)r * sB;
    const float* bias = biasAll + (long)r * sBias;
    float* C = Call + (long)r * sC;

    __shared__ float As[2][128][20];
    __shared__ float Bs[2][16][136];

    const int t = threadIdx.x;
    const int lane = t & 31;
    const int warp = t >> 5;
    const int wm = (warp >> 2) * 64;
    const int wn = (warp & 3) * 32;
    const long bm = (long)blockIdx.y * 128;
    const int bn = blockIdx.x * 128;

    const int aRow = t >> 2;
    const int aCol = (t & 3) << 2;
    const int bRow = t >> 5;
    const int bCol = (t & 31) << 2;
    const bool bValid = (bn + bCol) < N;
    const int bnc = bValid ? bn + bCol : 0;

    const int gid = lane >> 2;
    const int tig = lane & 3;

    float acc[4][4][4];
#pragma unroll
    for (int i = 0; i < 4; i++)
#pragma unroll
        for (int j = 0; j < 4; j++)
#pragma unroll
            for (int c = 0; c < 4; c++) acc[i][j][c] = 0.f;

    const int KT = K / 16;

    {
        cp16(&As[0][aRow][aCol], A + (bm + aRow) * (long)K + aCol, true);
        cp16(&As[0][aRow + 64][aCol], A + (bm + aRow + 64) * (long)K + aCol, true);
        cp16(&Bs[0][bRow][bCol], B + (long)bRow * N + bnc, bValid);
        cp16(&Bs[0][bRow + 8][bCol], B + (long)(bRow + 8) * N + bnc, bValid);
        asm volatile("cp.async.commit_group;" ::: "memory");
        asm volatile("cp.async.wait_group 0;" ::: "memory");
        __syncthreads();
    }

    for (int kt = 0; kt < KT; kt++) {
        const int cb = kt & 1, nb = (kt + 1) & 1;
        if (kt + 1 < KT) {
            long ko = (long)(kt + 1) * 16;
            cp16(&As[nb][aRow][aCol], A + (bm + aRow) * (long)K + ko + aCol, true);
            cp16(&As[nb][aRow + 64][aCol], A + (bm + aRow + 64) * (long)K + ko + aCol, true);
            cp16(&Bs[nb][bRow][bCol], B + (ko + bRow) * (long)N + bnc, bValid);
            cp16(&Bs[nb][bRow + 8][bCol], B + (ko + bRow + 8) * (long)N + bnc, bValid);
            asm volatile("cp.async.commit_group;" ::: "memory");
        }
#pragma unroll
        for (int k8 = 0; k8 < 2; k8++) {
            const int k0 = k8 * 8;
            unsigned a[4][4], b[4][2];
#pragma unroll
            for (int tm = 0; tm < 4; tm++) {
                int m = wm + tm * 16 + gid;
                a[tm][0] = tf32(As[cb][m][k0 + tig]);
                a[tm][1] = tf32(As[cb][m + 8][k0 + tig]);
                a[tm][2] = tf32(As[cb][m][k0 + tig + 4]);
                a[tm][3] = tf32(As[cb][m + 8][k0 + tig + 4]);
            }
#pragma unroll
            for (int tn = 0; tn < 4; tn++) {
                int n = wn + tn * 8 + gid;
                b[tn][0] = tf32(Bs[cb][k0 + tig][n]);
                b[tn][1] = tf32(Bs[cb][k0 + tig + 4][n]);
            }
#pragma unroll
            for (int tm = 0; tm < 4; tm++)
#pragma unroll
                for (int tn = 0; tn < 4; tn++)
                    mma8(acc[tm][tn], a[tm], b[tn]);
        }
        if (kt + 1 < KT)
            asm volatile("cp.async.wait_group 0;" ::: "memory");
        __syncthreads();
    }

#pragma unroll
    for (int tm = 0; tm < 4; tm++) {
        long row0 = bm + wm + tm * 16 + gid;
#pragma unroll
        for (int tn = 0; tn < 4; tn++) {
            int col = bn + wn + tn * 8 + tig * 2;
            if (col < N) {
                float bs0 = bias[col], bs1 = bias[col + 1];
#pragma unroll
                for (int h = 0; h < 2; h++) {
                    long row = row0 + h * 8;
                    float u0 = acc[tm][tn][h * 2 + 0] + bs0;
                    float u1 = acc[tm][tn][h * 2 + 1] + bs1;
                    if (ACT == 1) { u0 = fmaxf(u0, 0.f); u1 = fmaxf(u1, 0.f); }
                    else if (ACT == 2) { u0 = (u0 > 0.f) ? u0 : 0.01f * u0;
                                         u1 = (u1 > 0.f) ? u1 : 0.01f * u1; }
                    else { u0 = tanhf(u0); u1 = tanhf(u1); }
                    C[row * ldc + col] = u0;
                    C[row * ldc + col + 1] = u1;
                }
            }
        }
    }
}

// pred_missing head
__global__ void k_dw3(const float* __restrict__ z, const float* __restrict__ W,
                      const float* __restrict__ b, float* __restrict__ out) {
    int i = blockIdx.x * blockDim.x + threadIdx.x;
    if (i >= 3 * SSED) return;
    int r = i / SSED;
    int s = i % SSED;
    const float* zz = z + ((long)r * SSED + s) * 32;
    const float* w = W + r * 32;
    float acc = b[r];
#pragma unroll
    for (int k = 0; k < 32; k++) acc = fmaf(zz[k], w[k], acc);
    out[((long)r * SSED + s) * 321] = fmaxf(acc, 0.f);
}

// ---------------- host launch ----------------------------------------------
extern "C" void kernel_launch(void* const* d_in, const int* in_sizes, int n_in,
                              void* d_out, int out_size) {
    static const int MAP_DICT[27] = {0,1,2,3,4,5,6,7,8,9,10,11,12,13,14,15,16,17,18,19,20,21,22,23,24,25,26};
    static const int MAP_SIG[27]  = {0,1,20,21,22,23,24,25,26,2,3,4,5,6,7,8,9,10,11,12,13,14,15,16,17,18,19};
    static const int MAP_ALPHA[27]= {26,21,22,23,12,24,13,25,14,0,3,1,4,2,5,6,9,7,10,8,11,15,18,16,19,17,20};
    const int* MAP = MAP_DICT;
    if (n_in >= 3) {
        if (in_sizes[2] == 12288) MAP = MAP_SIG;
        else if (in_sizes[2] == 4096) MAP = MAP_ALPHA;
    }

    const float* x     = (const float*)d_in[MAP[0]];
    const float* noise = (const float*)d_in[MAP[1]];
    const int* src[3]  = {(const int*)d_in[MAP[3]], (const int*)d_in[MAP[5]], (const int*)d_in[MAP[7]]};
    const int* dst[3]  = {(const int*)d_in[MAP[4]], (const int*)d_in[MAP[6]], (const int*)d_in[MAP[8]]};
    const float* Wc1   = (const float*)d_in[MAP[9]];
    const float* bc1   = (const float*)d_in[MAP[10]];
    const float* Wc2   = (const float*)d_in[MAP[11]];
    const float* bc2   = (const float*)d_in[MAP[12]];
    const float* Wlin  = (const float*)d_in[MAP[13]];
    const float* blin  = (const float*)d_in[MAP[14]];
    const float* dW1   = (const float*)d_in[MAP[15]];
    const float* db1   = (const float*)d_in[MAP[16]];
    const float* dW2   = (const float*)d_in[MAP[17]];
    const float* db2   = (const float*)d_in[MAP[18]];
    const float* dW3   = (const float*)d_in[MAP[19]];
    const float* db3   = (const float*)d_in[MAP[20]];
    const float* fW1   = (const float*)d_in[MAP[21]];
    const float* fb1   = (const float*)d_in[MAP[22]];
    const float* fW2   = (const float*)d_in[MAP[23]];
    const float* fb2   = (const float*)d_in[MAP[24]];
    const float* fW3   = (const float*)d_in[MAP[25]];
    const float* fb3   = (const float*)d_in[MAP[26]];
    float* out = (float*)d_out;

    float *pS, *pH1, *pH2, *pZ2;
    __half *pXh, *pHsh, *pY1h, *pY2h, *pWd1h, *pWd2h, *pWf1h, *pWf2h, *pWf3h;
    cudaGetSymbolAddress((void**)&pS,    g_S);
    cudaGetSymbolAddress((void**)&pH1,   g_h1);
    cudaGetSymbolAddress((void**)&pH2,   g_h2);
    cudaGetSymbolAddress((void**)&pZ2,   g_zd2);
    cudaGetSymbolAddress((void**)&pXh,   g_xh);
    cudaGetSymbolAddress((void**)&pHsh,  g_hsh);
    cudaGetSymbolAddress((void**)&pY1h,  g_y1h);
    cudaGetSymbolAddress((void**)&pY2h,  g_y2h);
    cudaGetSymbolAddress((void**)&pWd1h, g_wd1h);
    cudaGetSymbolAddress((void**)&pWd2h, g_wd2h);
    cudaGetSymbolAddress((void**)&pWf1h, g_wf1h);
    cudaGetSymbolAddress((void**)&pWf2h, g_wf2h);
    cudaGetSymbolAddress((void**)&pWf3h, g_wf3h);

    // ----- fused conversions + degree count (g_cur pre-zeroed) -----
    k_convert<<<(int)((CVT_TOT + 255) / 256), 256>>>(x, dW1, dW2, fW1, fW2, fW3,
                                                     dst[0], dst[1], dst[2]);

    // ----- CSR scan + fill -----
    k_scan<<<3, 1024>>>();
    {
        dim3 g((EE + 255) / 256, 3);
        k_fill<<<g, 256>>>(src[0], dst[0], src[1], dst[1], src[2], dst[2]);
    }

    // ----- conv layer 1 (fp16 gather, MLP=8 via split groups; re-zeroes g_cur) -----
    {
        dim3 g((NN + 15) / 16, 3);
        k_gather_h<<<g, 256>>>(pXh);
    }
    k_tgemm<1><<<dim3(1, NNP / 128, 1), 256>>>(pS, Wc1, bc1, pH1,
                                               NNP, 64, 192, 0, 0, 0, 0, 64);

    // ----- conv layer 2 -----
    {
        dim3 g(SSED / 16, 3);
        k_gather<<<g, 256>>>(pH1, SSED);
    }
    k_tgemm<1><<<dim3(1, SSED / 128, 1), 256>>>(pS, Wc2, bc2, pH2,
                                                SSED, 64, 192, 0, 0, 0, 0, 64);

    // ----- final linear (fp16 hs) -----
    k_final<<<2048, 256>>>(Wlin, blin, noise);

    // ----- decoder: pred_missing -----
    dim3 g1(2, SSED / 128, 3);
    k_hgemm<2, 1><<<g1, 256>>>(pHsh, pWd1h, db1, pY1h, SSED, 256, 64,
                               0, (long)64 * 256, 256, (long)SSED * 256, 256);
    dim3 g2(1, SSED / 128, 3);
    k_hgemm<2, 0><<<g2, 256>>>(pY1h, pWd2h, db2, pZ2, SSED, 32, 256,
                               (long)SSED * 256, (long)256 * 32, 32,
                               (long)SSED * 32, 32);
    k_dw3<<<(3 * SSED + 255) / 256, 256>>>(pZ2, dW3, db3, out);

    // ----- decoder: pred_feat -----
    k_hgemm<1, 1><<<g1, 256>>>(pHsh, pWf1h, fb1, pY1h, SSED, 256, 64,
                               0, (long)64 * 256, 256, (long)SSED * 256, 256);
    dim3 g3(16, SSED / 128, 3);
    k_hgemm<1, 1><<<g3, 256>>>(pY1h, pWf2h, fb2, pY2h, SSED, 2048, 256,
                               (long)SSED * 256, (long)256 * 2048, 2048,
                               (long)SSED * 2048, 2048);
    dim3 g4(3, SSED / 128, 3);
    k_hgemm<3, 0><<<g4, 256>>>(pY2h, pWf3h, fb3, out + 1, SSED, 320, 2048,
                               (long)SSED * 2048, (long)2048 * 320, 320,
                               (long)SSED * 321, 321);
}